// round 8
// baseline (speedup 1.0000x reference)
#include <cuda_runtime.h>
#include <cuda_bf16.h>
#include <math.h>
#include <stdint.h>

// Problem constants
#define Bq   2
#define Sq   1024
#define Dq   512
#define Fq   2048
#define MF   (Bq*Sq)          // 2048 GEMM rows
#define FLAT (Sq*Dq)          // 524288 per-batch flat size (2^19)
#define TOT  (Bq*FLAT)        // 1048576
#define LAMv 1e-4f

// ---------------- scratch (no allocations allowed) ----------------
__device__ float g_xb[(size_t)MF*Fq];   // x@Wx + b1 (16MB)
__device__ float g_z [TOT];             // current z (fp32)
__device__ float g_f [TOT];             // f(z) (only used i>=5)
__device__ float g_Gh[4][TOT];          // g history, circular
__device__ float g_Zh[4][TOT];          // z history, circular
__device__ float g_red[2*14];
__device__ float g_gamma[2*4];

// bf16 hi/lo planes (error-compensated split operands)
__device__ __nv_bfloat16 g_W1T[2][(size_t)Fq*Dq];  // [N=2048][K=512]
__device__ __nv_bfloat16 g_WxT[2][(size_t)Fq*Dq];
__device__ __nv_bfloat16 g_W2T[2][(size_t)Dq*Fq];  // [512][2048]
__device__ __nv_bfloat16 g_xp [2][TOT];
__device__ __nv_bfloat16 g_zp [2][TOT];
__device__ __nv_bfloat16 g_hp [2][(size_t)MF*Fq];

// ======================= helpers =======================
__device__ __forceinline__ uint32_t smem_u32(const void* p){
    uint32_t a;
    asm("{ .reg .u64 t; cvta.to.shared.u64 t, %1; cvt.u32.u64 %0, t; }" : "=r"(a) : "l"(p));
    return a;
}
#define SWZ64(o) ((o) ^ (((o) >> 3) & 0x30))

__device__ __forceinline__ void ldm4(uint32_t* r, uint32_t addr){
    asm volatile("ldmatrix.sync.aligned.m8n8.x4.shared.b16 {%0,%1,%2,%3}, [%4];"
        : "=r"(r[0]), "=r"(r[1]), "=r"(r[2]), "=r"(r[3]) : "r"(addr));
}
__device__ __forceinline__ void mma_bf16(float* c, const uint32_t* a, const uint32_t* b){
    asm volatile("mma.sync.aligned.m16n8k16.row.col.f32.bf16.bf16.f32 "
        "{%0,%1,%2,%3}, {%4,%5,%6,%7}, {%8,%9}, {%0,%1,%2,%3};"
        : "+f"(c[0]), "+f"(c[1]), "+f"(c[2]), "+f"(c[3])
        : "r"(a[0]), "r"(a[1]), "r"(a[2]), "r"(a[3]), "r"(b[0]), "r"(b[1]));
}
__device__ __forceinline__ void cpasync16(uint32_t dst, const void* src){
    asm volatile("cp.async.cg.shared.global [%0], [%1], 16;" :: "r"(dst), "l"(src));
}
__device__ __forceinline__ void cpcommit(){ asm volatile("cp.async.commit_group;" ::: "memory"); }
template<int N> __device__ __forceinline__ void cpwait(){
    asm volatile("cp.async.wait_group %0;" :: "n"(N) : "memory");
}
__device__ __forceinline__ __nv_bfloat162 split_hi(float a, float b){
    return __floats2bfloat162_rn(a, b);
}
__device__ __forceinline__ __nv_bfloat162 split_lo(float a, float b, __nv_bfloat162 h){
    return __floats2bfloat162_rn(a - __bfloat162float(h.x), b - __bfloat162float(h.y));
}

// ======================= pipelined split-bf16 mma.sync GEMM =======================
// CTA tile 128(M) x 64(N), K-slab 32, SW64 swizzle, 3-stage cp.async, 2 CTAs/SM.
// MODE 0: C fp32 = acc + bias[n]
// MODE 1: t = tanh(acc + Dm[m][n]); write Chp/Clp bf16 hi/lo planes
// MODE 2: f = acc + bias[n]; fused upd_simple (C holds z in/out)
template<int MODE>
__global__ __launch_bounds__(256, 2) void gemm_p(
    const __nv_bfloat16* __restrict__ Ahp, const __nv_bfloat16* __restrict__ Alp,
    const __nv_bfloat16* __restrict__ Bhp, const __nv_bfloat16* __restrict__ Blp,
    const float* __restrict__ bias, const float* __restrict__ Dm,
    float* __restrict__ C,
    __nv_bfloat16* __restrict__ Chp, __nv_bfloat16* __restrict__ Clp,
    float* __restrict__ Ghs, float* __restrict__ Zhs,
    int K, int ldn)
{
    constexpr int APL = 128 * 32 * 2;          // A plane per stage (8 KB)
    constexpr int BPL = 64  * 32 * 2;          // B plane per stage (4 KB)
    constexpr int STG = 2 * APL + 2 * BPL;     // 24 KB stage
    constexpr int NT  = 4;

    extern __shared__ char dynraw[];
    char* dyn = (char*)(((uintptr_t)dynraw + 127) & ~(uintptr_t)127);

    const int tid  = threadIdx.x;
    const int wid  = tid >> 5;
    const int lane = tid & 31;
    const int m0w  = (wid & 3) * 32;
    const int n0w  = (wid >> 2) * 32;
    const int NS   = K >> 5;

    float acc[2][NT][4];
#pragma unroll
    for (int mt = 0; mt < 2; mt++)
#pragma unroll
        for (int nt = 0; nt < NT; nt++)
#pragma unroll
            for (int v = 0; v < 4; v++) acc[mt][nt][v] = 0.f;

    auto issue = [&](int s, int st){
        uint32_t ba = smem_u32(dyn + st * STG);
        const __nv_bfloat16* ap[2] = { Ahp, Alp };
#pragma unroll
        for (int p = 0; p < 2; p++)
#pragma unroll
            for (int it = 0; it < 2; it++) {
                int c = tid + it * 256;
                int row = c >> 2, u = c & 3;
                const void* src = ap[p] + (size_t)(blockIdx.y * 128 + row) * K + s * 32 + u * 8;
                cpasync16(ba + p * APL + SWZ64((uint32_t)(row * 64 + u * 16)), src);
            }
        const __nv_bfloat16* bp[2] = { Bhp, Blp };
#pragma unroll
        for (int p = 0; p < 2; p++) {
            int row = tid >> 2, u = tid & 3;
            const void* src = bp[p] + (size_t)(blockIdx.x * 64 + row) * K + s * 32 + u * 8;
            cpasync16(ba + 2 * APL + p * BPL + SWZ64((uint32_t)(row * 64 + u * 16)), src);
        }
    };

    issue(0, 0); cpcommit();
    issue(1, 1); cpcommit();

    const int arow = lane & 15;
    const int brow = (lane & 7) | ((lane >> 1) & 8);
    const int asel = lane >> 4;
    const int bsel = (lane >> 3) & 1;

    for (int s = 0; s < NS; s++) {
        const int st = s % 3;
        if (s + 2 < NS) issue(s + 2, (s + 2) % 3);
        cpcommit();
        cpwait<2>();
        __syncthreads();

        const uint32_t bAh = smem_u32(dyn + st * STG);
        const uint32_t bAl = bAh + APL;
        const uint32_t bBh = bAh + 2 * APL;
        const uint32_t bBl = bBh + BPL;

#pragma unroll
        for (int ks = 0; ks < 2; ks++) {
            uint32_t ah[2][4], al[2][4];
            const int au = (ks << 1) + asel;
#pragma unroll
            for (int mt = 0; mt < 2; mt++) {
                uint32_t off = SWZ64((uint32_t)((m0w + mt * 16 + arow) * 64 + au * 16));
                ldm4(ah[mt], bAh + off);
                ldm4(al[mt], bAl + off);
            }
            uint32_t bh[NT][2], bl[NT][2];
            const int bu = (ks << 1) + bsel;
#pragma unroll
            for (int np = 0; np < NT / 2; np++) {
                uint32_t off = SWZ64((uint32_t)((n0w + np * 16 + brow) * 64 + bu * 16));
                uint32_t r[4];
                ldm4(r, bBh + off);
                bh[2*np][0] = r[0]; bh[2*np][1] = r[1];
                bh[2*np+1][0] = r[2]; bh[2*np+1][1] = r[3];
                ldm4(r, bBl + off);
                bl[2*np][0] = r[0]; bl[2*np][1] = r[1];
                bl[2*np+1][0] = r[2]; bl[2*np+1][1] = r[3];
            }
#pragma unroll
            for (int mt = 0; mt < 2; mt++)
#pragma unroll
                for (int nt = 0; nt < NT; nt++) {
                    mma_bf16(acc[mt][nt], ah[mt], bh[nt]);
                    mma_bf16(acc[mt][nt], ah[mt], bl[nt]);
                    mma_bf16(acc[mt][nt], al[mt], bh[nt]);
                }
        }
        __syncthreads();
    }

    // ---------- epilogue ----------
#pragma unroll
    for (int mt = 0; mt < 2; mt++) {
        const int gm = blockIdx.y * 128 + m0w + mt * 16 + (lane >> 2);
#pragma unroll
        for (int nt = 0; nt < NT; nt++) {
            const int gn = blockIdx.x * 64 + n0w + nt * 8 + ((lane & 3) << 1);
            const size_t o0 = (size_t)gm * ldn + gn;
            const size_t o1 = (size_t)(gm + 8) * ldn + gn;
            if (MODE == 0) {
                float2 bv = *(const float2*)(bias + gn);
                float2 r0, r1;
                r0.x = acc[mt][nt][0] + bv.x;  r0.y = acc[mt][nt][1] + bv.y;
                r1.x = acc[mt][nt][2] + bv.x;  r1.y = acc[mt][nt][3] + bv.y;
                *(float2*)(C + o0) = r0;
                *(float2*)(C + o1) = r1;
            } else if (MODE == 1) {
                float2 d0 = *(const float2*)(Dm + o0);
                float2 d1 = *(const float2*)(Dm + o1);
                float t0 = tanhf(acc[mt][nt][0] + d0.x);
                float t1 = tanhf(acc[mt][nt][1] + d0.y);
                float t2 = tanhf(acc[mt][nt][2] + d1.x);
                float t3 = tanhf(acc[mt][nt][3] + d1.y);
                __nv_bfloat162 h0 = split_hi(t0, t1);
                __nv_bfloat162 h1 = split_hi(t2, t3);
                *(__nv_bfloat162*)(Chp + o0) = h0;
                *(__nv_bfloat162*)(Chp + o1) = h1;
                *(__nv_bfloat162*)(Clp + o0) = split_lo(t0, t1, h0);
                *(__nv_bfloat162*)(Clp + o1) = split_lo(t2, t3, h1);
            } else {
                float2 bv = *(const float2*)(bias + gn);
                float f0 = acc[mt][nt][0] + bv.x;
                float f1 = acc[mt][nt][1] + bv.y;
                float f2 = acc[mt][nt][2] + bv.x;
                float f3 = acc[mt][nt][3] + bv.y;
                float2 z0 = *(const float2*)(C + o0);
                float2 z1 = *(const float2*)(C + o1);
                float2 gg0 = { f0 - z0.x, f1 - z0.y };
                float2 gg1 = { f2 - z1.x, f3 - z1.y };
                *(float2*)(Ghs + o0) = gg0;
                *(float2*)(Ghs + o1) = gg1;
                *(float2*)(Zhs + o0) = z0;
                *(float2*)(Zhs + o1) = z1;
                float2 w0 = { f0, f1 }, w1 = { f2, f3 };
                *(float2*)(C + o0) = w0;
                *(float2*)(C + o1) = w1;
                __nv_bfloat162 h0 = split_hi(f0, f1);
                __nv_bfloat162 h1 = split_hi(f2, f3);
                *(__nv_bfloat162*)(Chp + o0) = h0;
                *(__nv_bfloat162*)(Chp + o1) = h1;
                *(__nv_bfloat162*)(Clp + o0) = split_lo(f0, f1, h0);
                *(__nv_bfloat162*)(Clp + o1) = split_lo(f2, f3, h1);
            }
        }
    }
}

// ---------------- one-time converters ----------------
__global__ void conv_wT(const float* __restrict__ W,
                        __nv_bfloat16* __restrict__ Th, __nv_bfloat16* __restrict__ Tl,
                        int K, int N)
{
    __shared__ float t[32][33];
    int n0 = blockIdx.x * 32, k0 = blockIdx.y * 32;
    int tx = threadIdx.x, ty = threadIdx.y;
#pragma unroll
    for (int r = 0; r < 32; r += 8)
        t[ty + r][tx] = W[(size_t)(k0 + ty + r) * N + n0 + tx];
    __syncthreads();
#pragma unroll
    for (int r = 0; r < 32; r += 8) {
        float v = t[tx][ty + r];
        __nv_bfloat16 hb = __float2bfloat16(v);
        size_t o = (size_t)(n0 + ty + r) * K + k0 + tx;
        Th[o] = hb;
        Tl[o] = __float2bfloat16(v - __bfloat162float(hb));
    }
}
__global__ void conv_plane(const float* __restrict__ X,
                           __nv_bfloat16* __restrict__ Xh, __nv_bfloat16* __restrict__ Xl)
{
    int i = blockIdx.x * blockDim.x + threadIdx.x;
    float4 v = ((const float4*)X)[i];
    __nv_bfloat162 h01 = split_hi(v.x, v.y), h23 = split_hi(v.z, v.w);
    ((__nv_bfloat162*)Xh)[i*2]   = h01;
    ((__nv_bfloat162*)Xh)[i*2+1] = h23;
    ((__nv_bfloat162*)Xl)[i*2]   = split_lo(v.x, v.y, h01);
    ((__nv_bfloat162*)Xl)[i*2+1] = split_lo(v.z, v.w, h23);
}

// ---------------- iteration 0: h = tanh(xb) ----------------
__global__ void tanh_map(const float* __restrict__ src,
                         __nv_bfloat16* __restrict__ Hh, __nv_bfloat16* __restrict__ Hl)
{
    int i = blockIdx.x * blockDim.x + threadIdx.x;
    float4 v = ((const float4*)src)[i];
    v.x = tanhf(v.x); v.y = tanhf(v.y); v.z = tanhf(v.z); v.w = tanhf(v.w);
    __nv_bfloat162 h01 = split_hi(v.x, v.y), h23 = split_hi(v.z, v.w);
    ((__nv_bfloat162*)Hh)[i*2]   = h01;
    ((__nv_bfloat162*)Hh)[i*2+1] = h23;
    ((__nv_bfloat162*)Hl)[i*2]   = split_lo(v.x, v.y, h01);
    ((__nv_bfloat162*)Hl)[i*2+1] = split_lo(v.z, v.w, h23);
}

// ---------------- Anderson: HTH/HTy reduction ----------------
__global__ void reduce_k(const float* __restrict__ f, const float* __restrict__ z,
                         int s1, int s2, int s3, int s4)
{
    int b = blockIdx.y;
    int base = b * (FLAT / 4);
    const float4* fp = (const float4*)f + base;
    const float4* zp = (const float4*)z + base;
    const float4* h1 = (const float4*)g_Gh[s1] + base;
    const float4* h2 = (const float4*)g_Gh[s2] + base;
    const float4* h3 = (const float4*)g_Gh[s3] + base;
    const float4* h4 = (const float4*)g_Gh[s4] + base;

    float acc[14];
#pragma unroll
    for (int v = 0; v < 14; v++) acc[v] = 0.f;

    int n4 = FLAT / 4;
    for (int i = blockIdx.x * blockDim.x + threadIdx.x; i < n4;
         i += gridDim.x * blockDim.x) {
        float4 fv = fp[i], zv = zp[i];
        float4 a1 = h1[i], a2 = h2[i], a3 = h3[i], a4 = h4[i];
        const float* fa = (const float*)&fv; const float* za = (const float*)&zv;
        const float* p1 = (const float*)&a1; const float* p2 = (const float*)&a2;
        const float* p3 = (const float*)&a3; const float* p4 = (const float*)&a4;
#pragma unroll
        for (int c = 0; c < 4; c++) {
            float g  = fa[c] - za[c];
            float d0 = g - p1[c];
            float d1 = g - p2[c];
            float d2 = g - p3[c];
            float d3 = g - p4[c];
            acc[0] += d0 * d0; acc[1] += d0 * d1; acc[2] += d0 * d2; acc[3] += d0 * d3;
            acc[4] += d1 * d1; acc[5] += d1 * d2; acc[6] += d1 * d3;
            acc[7] += d2 * d2; acc[8] += d2 * d3; acc[9] += d3 * d3;
            acc[10] += d0 * g; acc[11] += d1 * g; acc[12] += d2 * g; acc[13] += d3 * g;
        }
    }
#pragma unroll
    for (int v = 0; v < 14; v++)
#pragma unroll
        for (int o = 16; o > 0; o >>= 1)
            acc[v] += __shfl_down_sync(0xffffffffu, acc[v], o);

    __shared__ float sm[8][14];
    int w = threadIdx.x / 32, lane = threadIdx.x % 32;
    if (lane == 0) {
#pragma unroll
        for (int v = 0; v < 14; v++) sm[w][v] = acc[v];
    }
    __syncthreads();
    if (threadIdx.x < 14) {
        float s = 0.f;
#pragma unroll
        for (int w2 = 0; w2 < 8; w2++) s += sm[w2][threadIdx.x];
        atomicAdd(&g_red[b * 14 + threadIdx.x], s);
    }
}

// ---------------- 4x4 Schur-complement solve ----------------
__device__ __forceinline__ void inv2x2d(const float m[4], float o[4])
{
    float invDet = 1.f / (m[0] * m[3] - m[1] * m[2] + 1e-6f);
    o[0] =  m[3] * invDet; o[1] = -m[1] * invDet;
    o[2] = -m[2] * invDet; o[3] =  m[0] * invDet;
}
__device__ __forceinline__ void mul2x2d(const float a[4], const float b[4], float o[4])
{
    o[0] = a[0] * b[0] + a[1] * b[2]; o[1] = a[0] * b[1] + a[1] * b[3];
    o[2] = a[2] * b[0] + a[3] * b[2]; o[3] = a[2] * b[1] + a[3] * b[3];
}

__global__ void solve_k()
{
    int b = threadIdx.x;
    if (b >= 2) return;
    const float* r = &g_red[b * 14];
    float H[4][4];
    H[0][0] = r[0] + LAMv; H[0][1] = r[1];        H[0][2] = r[2];        H[0][3] = r[3];
    H[1][0] = r[1];        H[1][1] = r[4] + LAMv; H[1][2] = r[5];        H[1][3] = r[6];
    H[2][0] = r[2];        H[2][1] = r[5];        H[2][2] = r[7] + LAMv; H[2][3] = r[8];
    H[3][0] = r[3];        H[3][1] = r[6];        H[3][2] = r[8];        H[3][3] = r[9] + LAMv;
    float y[4] = { r[10], r[11], r[12], r[13] };

    float A_[4] = { H[0][0], H[0][1], H[1][0], H[1][1] };
    float Bb[4] = { H[0][2], H[0][3], H[1][2], H[1][3] };
    float C_[4] = { H[2][0], H[2][1], H[3][0], H[3][1] };
    float Dd[4] = { H[2][2], H[2][3], H[3][2], H[3][3] };

    float Ai[4];   inv2x2d(A_, Ai);
    float CAi[4];  mul2x2d(C_, Ai, CAi);
    float CAiB[4]; mul2x2d(CAi, Bb, CAiB);
    float Sch[4]  = { Dd[0] - CAiB[0], Dd[1] - CAiB[1], Dd[2] - CAiB[2], Dd[3] - CAiB[3] };
    float Si[4];   inv2x2d(Sch, Si);
    float SiCAi[4]; mul2x2d(Si, CAi, SiCAi);
    float AiB[4];   mul2x2d(Ai, Bb, AiB);
    float t11[4];   mul2x2d(AiB, SiCAi, t11);
    float b11[4] = { Ai[0] + t11[0], Ai[1] + t11[1], Ai[2] + t11[2], Ai[3] + t11[3] };
    float b12[4];   mul2x2d(AiB, Si, b12);
    b12[0] = -b12[0]; b12[1] = -b12[1]; b12[2] = -b12[2]; b12[3] = -b12[3];

    float inv[4][4] = {
        { b11[0],  b11[1],  b12[0],  b12[1] },
        { b11[2],  b11[3],  b12[2],  b12[3] },
        { -SiCAi[0], -SiCAi[1], Si[0], Si[1] },
        { -SiCAi[2], -SiCAi[3], Si[2], Si[3] }
    };
#pragma unroll
    for (int j = 0; j < 4; j++)
        g_gamma[b * 4 + j] = inv[j][0] * y[0] + inv[j][1] * y[1]
                           + inv[j][2] * y[2] + inv[j][3] * y[3];
}

// ---------------- Anderson mixed update (+ z planes) ----------------
__global__ void upd_anderson(const float* __restrict__ f, float* __restrict__ z,
                             float* __restrict__ dst,
                             int s1, int s2, int s3, int s4, int sw)
{
    int i = blockIdx.x * blockDim.x + threadIdx.x;
    int b = i >> 17;
    float ga0 = g_gamma[b * 4 + 0];
    float ga1 = g_gamma[b * 4 + 1];
    float ga2 = g_gamma[b * 4 + 2];
    float ga3 = g_gamma[b * 4 + 3];

    float4 fv = ((const float4*)f)[i];
    float4 zv = ((const float4*)z)[i];
    float4 G1 = ((const float4*)g_Gh[s1])[i];
    float4 G2 = ((const float4*)g_Gh[s2])[i];
    float4 G3 = ((const float4*)g_Gh[s3])[i];
    float4 G4 = ((const float4*)g_Gh[s4])[i];
    float4 Z1 = ((const float4*)g_Zh[s1])[i];
    float4 Z2 = ((const float4*)g_Zh[s2])[i];
    float4 Z3 = ((const float4*)g_Zh[s3])[i];
    float4 Z4 = ((const float4*)g_Zh[s4])[i];

    float4 gv, ov;
    float* fa = (float*)&fv;  float* za = (float*)&zv;
    float* g1 = (float*)&G1;  float* g2 = (float*)&G2;
    float* g3 = (float*)&G3;  float* g4 = (float*)&G4;
    float* z1 = (float*)&Z1;  float* z2 = (float*)&Z2;
    float* z3 = (float*)&Z3;  float* z4 = (float*)&Z4;
    float* gva = (float*)&gv; float* ova = (float*)&ov;

#pragma unroll
    for (int c = 0; c < 4; c++) {
        float zc = za[c];
        float g  = fa[c] - zc;
        float corr = ga0 * ((zc - z1[c]) + (g - g1[c]))
                   + ga1 * ((zc - z2[c]) + (g - g2[c]))
                   + ga2 * ((zc - z3[c]) + (g - g3[c]))
                   + ga3 * ((zc - z4[c]) + (g - g4[c]));
        gva[c] = g;
        ova[c] = zc + g - corr;
    }
    ((float4*)g_Gh[sw])[i] = gv;
    ((float4*)g_Zh[sw])[i] = zv;
    ((float4*)dst)[i] = ov;
    __nv_bfloat162 h01 = split_hi(ov.x, ov.y), h23 = split_hi(ov.z, ov.w);
    ((__nv_bfloat162*)g_zp[0])[i*2]   = h01;
    ((__nv_bfloat162*)g_zp[0])[i*2+1] = h23;
    ((__nv_bfloat162*)g_zp[1])[i*2]   = split_lo(ov.x, ov.y, h01);
    ((__nv_bfloat162*)g_zp[1])[i*2+1] = split_lo(ov.z, ov.w, h23);
}

// ---------------- launcher ----------------
extern "C" void kernel_launch(void* const* d_in, const int* in_sizes, int n_in,
                              void* d_out, int out_size)
{
    (void)in_sizes; (void)n_in; (void)out_size;
    const float* x  = (const float*)d_in[0];
    const float* W1 = (const float*)d_in[1];
    const float* Wx = (const float*)d_in[2];
    const float* b1 = (const float*)d_in[3];
    const float* W2 = (const float*)d_in[4];
    const float* b2 = (const float*)d_in[5];
    float* out = (float*)d_out;

    float *xb, *z, *f, *red, *Gh0, *Zh0;
    cudaGetSymbolAddress((void**)&xb,  g_xb);
    cudaGetSymbolAddress((void**)&z,   g_z);
    cudaGetSymbolAddress((void**)&f,   g_f);
    cudaGetSymbolAddress((void**)&red, g_red);
    cudaGetSymbolAddress((void**)&Gh0, g_Gh);
    cudaGetSymbolAddress((void**)&Zh0, g_Zh);
    __nv_bfloat16 *W1Th, *W1Tl, *WxTh, *WxTl, *W2Th, *W2Tl, *xh, *xl, *zh, *zl, *hh, *hl;
    cudaGetSymbolAddress((void**)&W1Th, g_W1T); W1Tl = W1Th + (size_t)Fq*Dq;
    cudaGetSymbolAddress((void**)&WxTh, g_WxT); WxTl = WxTh + (size_t)Fq*Dq;
    cudaGetSymbolAddress((void**)&W2Th, g_W2T); W2Tl = W2Th + (size_t)Dq*Fq;
    cudaGetSymbolAddress((void**)&xh,   g_xp);  xl   = xh   + TOT;
    cudaGetSymbolAddress((void**)&zh,   g_zp);  zl   = zh   + TOT;
    cudaGetSymbolAddress((void**)&hh,   g_hp);  hl   = hh   + (size_t)MF*Fq;

    const int DYN = 3 * (2*128*32*2 + 2*64*32*2) + 128;   // ~72 KB
    cudaFuncSetAttribute(gemm_p<0>, cudaFuncAttributeMaxDynamicSharedMemorySize, DYN);
    cudaFuncSetAttribute(gemm_p<1>, cudaFuncAttributeMaxDynamicSharedMemorySize, DYN);
    cudaFuncSetAttribute(gemm_p<2>, cudaFuncAttributeMaxDynamicSharedMemorySize, DYN);

    cudaMemsetAsync(z, 0, (size_t)TOT * sizeof(float));

    dim3 tb(32, 8);
    conv_wT<<<dim3(Fq/32, Dq/32), tb>>>(W1, W1Th, W1Tl, Dq, Fq);
    conv_wT<<<dim3(Fq/32, Dq/32), tb>>>(Wx, WxTh, WxTl, Dq, Fq);
    conv_wT<<<dim3(Dq/32, Fq/32), tb>>>(W2, W2Th, W2Tl, Fq, Dq);
    conv_plane<<<TOT/4/256, 256>>>(x, xh, xl);

    dim3 g1(Fq / 64, MF / 128);   // 32 x 16 = 512 CTAs
    dim3 g2(Dq / 64, MF / 128);   // 8 x 16  = 128 CTAs

    // xb = x @ Wx + b1
    gemm_p<0><<<g1, 256, DYN>>>(xh, xl, WxTh, WxTl, b1, nullptr, xb,
                                nullptr, nullptr, nullptr, nullptr, Dq, Fq);

    const int upd_blocks = TOT / 4 / 256;
    for (int i = 0; i < 12; i++) {
        // h = tanh(z @ W1 + xb)  -> bf16 hi/lo planes
        if (i == 0)
            tanh_map<<<(size_t)MF * Fq / 4 / 256, 256>>>(xb, hh, hl);
        else
            gemm_p<1><<<g1, 256, DYN>>>(zh, zl, W1Th, W1Tl, nullptr, xb, nullptr,
                                        hh, hl, nullptr, nullptr, Dq, Fq);
        // f = h @ W2 + b2
        if (i < 5) {
            gemm_p<2><<<g2, 256, DYN>>>(hh, hl, W2Th, W2Tl, b2, nullptr, z,
                                        zh, zl, Gh0 + (size_t)(i & 3) * TOT,
                                        Zh0 + (size_t)(i & 3) * TOT, Fq, Dq);
        } else {
            gemm_p<0><<<g2, 256, DYN>>>(hh, hl, W2Th, W2Tl, b2, nullptr, f,
                                        nullptr, nullptr, nullptr, nullptr, Fq, Dq);
            float* dst = (i == 11) ? out : z;
            cudaMemsetAsync(red, 0, 28 * sizeof(float));
            reduce_k<<<dim3(128, 2), 256>>>(f, z, (i - 1) & 3, (i - 2) & 3,
                                            (i - 3) & 3, (i - 4) & 3);
            solve_k<<<1, 32>>>();
            upd_anderson<<<upd_blocks, 256>>>(f, z, dst, (i - 1) & 3, (i - 2) & 3,
                                              (i - 3) & 3, (i - 4) & 3, i & 3);
        }
    }
}

// round 9
// speedup vs baseline: 1.1032x; 1.1032x over previous
#include <cuda_runtime.h>
#include <cuda_bf16.h>
#include <math.h>
#include <stdint.h>

// Problem constants
#define Bq   2
#define Sq   1024
#define Dq   512
#define Fq   2048
#define MF   (Bq*Sq)          // 2048 GEMM rows
#define FLAT (Sq*Dq)          // 524288 per-batch flat size (2^19)
#define TOT  (Bq*FLAT)        // 1048576
#define LAMv 1e-4f

// ---------------- scratch (no allocations allowed) ----------------
__device__ float g_xb[(size_t)MF*Fq];   // x@Wx + b1 (16MB)
__device__ float g_z [TOT];             // current z (fp32)
__device__ float g_f [TOT];             // f(z) (only used i>=5)
__device__ float g_Gh[4][TOT];          // g history, circular
__device__ float g_Zh[4][TOT];          // z history, circular
__device__ float g_red[2*14];
__device__ float g_gamma[2*4];

// bf16 hi/lo planes (error-compensated split operands)
__device__ __nv_bfloat16 g_W1T[2][(size_t)Fq*Dq];  // [N=2048][K=512]
__device__ __nv_bfloat16 g_WxT[2][(size_t)Fq*Dq];
__device__ __nv_bfloat16 g_W2T[2][(size_t)Dq*Fq];  // [512][2048]
__device__ __nv_bfloat16 g_xp [2][TOT];
__device__ __nv_bfloat16 g_zp [2][TOT];
__device__ __nv_bfloat16 g_hp [2][(size_t)MF*Fq];

// ======================= helpers =======================
__device__ __forceinline__ uint32_t smem_u32(const void* p){
    uint32_t a;
    asm("{ .reg .u64 t; cvta.to.shared.u64 t, %1; cvt.u32.u64 %0, t; }" : "=r"(a) : "l"(p));
    return a;
}
#define SWZ(o) ((o) ^ (((o) >> 3) & 0x70))

__device__ __forceinline__ void ldm4(uint32_t* r, uint32_t addr){
    asm volatile("ldmatrix.sync.aligned.m8n8.x4.shared.b16 {%0,%1,%2,%3}, [%4];"
        : "=r"(r[0]), "=r"(r[1]), "=r"(r[2]), "=r"(r[3]) : "r"(addr));
}
__device__ __forceinline__ void mma_bf16(float* c, const uint32_t* a, const uint32_t* b){
    asm volatile("mma.sync.aligned.m16n8k16.row.col.f32.bf16.bf16.f32 "
        "{%0,%1,%2,%3}, {%4,%5,%6,%7}, {%8,%9}, {%0,%1,%2,%3};"
        : "+f"(c[0]), "+f"(c[1]), "+f"(c[2]), "+f"(c[3])
        : "r"(a[0]), "r"(a[1]), "r"(a[2]), "r"(a[3]), "r"(b[0]), "r"(b[1]));
}
__device__ __forceinline__ void cpasync16(uint32_t dst, const void* src){
    asm volatile("cp.async.cg.shared.global [%0], [%1], 16;" :: "r"(dst), "l"(src));
}
__device__ __forceinline__ void cpcommit(){ asm volatile("cp.async.commit_group;" ::: "memory"); }
template<int N> __device__ __forceinline__ void cpwait(){
    asm volatile("cp.async.wait_group %0;" :: "n"(N) : "memory");
}
__device__ __forceinline__ __nv_bfloat162 split_hi(float a, float b){
    return __floats2bfloat162_rn(a, b);
}
__device__ __forceinline__ __nv_bfloat162 split_lo(float a, float b, __nv_bfloat162 h){
    return __floats2bfloat162_rn(a - __bfloat162float(h.x), b - __bfloat162float(h.y));
}

// ======================= pipelined split-bf16 mma.sync GEMM =======================
// R5-proven geometry: CTA tile 128(M) x BN, K-slab 64, SW128, 3-stage cp.async.
// A planes: [M x K] bf16 hi/lo.  B planes: [N x K] bf16 hi/lo.
// MODE 0: C fp32 = acc + bias[n]
// MODE 1: t = tanh(acc + Dm[m][n]); write Chp/Clp bf16 hi/lo planes
// MODE 2: f = acc + bias[n]; fused upd_simple:
//         g = f - C (C holds z in/out); Ghs=g, Zhs=z, C=f, Chp/Clp=split(f)
template<int BN, int MODE>
__global__ __launch_bounds__(256, 1) void gemm_p(
    const __nv_bfloat16* __restrict__ Ahp, const __nv_bfloat16* __restrict__ Alp,
    const __nv_bfloat16* __restrict__ Bhp, const __nv_bfloat16* __restrict__ Blp,
    const float* __restrict__ bias, const float* __restrict__ Dm,
    float* __restrict__ C,
    __nv_bfloat16* __restrict__ Chp, __nv_bfloat16* __restrict__ Clp,
    float* __restrict__ Ghs, float* __restrict__ Zhs,
    int K, int ldn)
{
    constexpr int ASTG = 128 * 64 * 2;         // one A plane per stage (16 KB)
    constexpr int BSTG = BN  * 64 * 2;         // one B plane per stage
    constexpr int STG  = 2 * ASTG + 2 * BSTG;  // stage size
    constexpr int BIT  = (BN * 8) / 256;       // B chunks per thread per plane
    constexpr int NT   = BN / 16;              // n8-tiles per warp

    extern __shared__ char dynraw[];
    char* dyn = (char*)(((uintptr_t)dynraw + 1023) & ~(uintptr_t)1023);

    const int tid  = threadIdx.x;
    const int wid  = tid >> 5;
    const int lane = tid & 31;
    const int m0w  = (wid & 3) * 32;
    const int n0w  = (wid >> 2) * (BN / 2);
    const int NS   = K >> 6;

    float acc[2][NT][4];
#pragma unroll
    for (int mt = 0; mt < 2; mt++)
#pragma unroll
        for (int nt = 0; nt < NT; nt++)
#pragma unroll
            for (int v = 0; v < 4; v++) acc[mt][nt][v] = 0.f;

    auto issue = [&](int s, int st){
        char* buf = dyn + st * STG;
        uint32_t ba = smem_u32(buf);
        const __nv_bfloat16* ap[2] = { Ahp, Alp };
#pragma unroll
        for (int p = 0; p < 2; p++)
#pragma unroll
            for (int it = 0; it < 4; it++) {
                int c = tid + it * 256;          // 0..1023
                int row = c >> 3, kc = c & 7;
                const void* src = ap[p] + (size_t)(blockIdx.y * 128 + row) * K + s * 64 + kc * 8;
                cpasync16(ba + p * ASTG + SWZ((uint32_t)(row * 128 + kc * 16)), src);
            }
        const __nv_bfloat16* bp[2] = { Bhp, Blp };
#pragma unroll
        for (int p = 0; p < 2; p++)
#pragma unroll
            for (int it = 0; it < BIT; it++) {
                int c = tid + it * 256;
                int row = c >> 3, kc = c & 7;
                const void* src = bp[p] + (size_t)(blockIdx.x * BN + row) * K + s * 64 + kc * 8;
                cpasync16(ba + 2 * ASTG + p * BSTG + SWZ((uint32_t)(row * 128 + kc * 16)), src);
            }
    };

    // prologue: 2 stages in flight
    issue(0, 0); cpcommit();
    issue(1, 1); cpcommit();

    const int arow = lane & 15;
    const int brow = (lane & 7) | ((lane >> 1) & 8);
    const int asel = lane >> 4;
    const int bsel = (lane >> 3) & 1;

    for (int s = 0; s < NS; s++) {
        const int st = s % 3;
        if (s + 2 < NS) issue(s + 2, (s + 2) % 3);
        cpcommit();
        cpwait<2>();                 // stage s landed
        __syncthreads();

        const uint32_t bAh = smem_u32(dyn + st * STG);
        const uint32_t bAl = bAh + ASTG;
        const uint32_t bBh = bAh + 2 * ASTG;
        const uint32_t bBl = bBh + BSTG;

#pragma unroll
        for (int ks = 0; ks < 4; ks++) {
            uint32_t ah[2][4], al[2][4];
            const int achunk = (ks << 1) + asel;
#pragma unroll
            for (int mt = 0; mt < 2; mt++) {
                uint32_t off = SWZ((uint32_t)((m0w + mt * 16 + arow) * 128 + achunk * 16));
                ldm4(ah[mt], bAh + off);
                ldm4(al[mt], bAl + off);
            }
            uint32_t bh[NT][2], bl[NT][2];
            const int bchunk = (ks << 1) + bsel;
#pragma unroll
            for (int np = 0; np < NT / 2; np++) {
                uint32_t off = SWZ((uint32_t)((n0w + np * 16 + brow) * 128 + bchunk * 16));
                uint32_t r[4];
                ldm4(r, bBh + off);
                bh[2*np][0] = r[0]; bh[2*np][1] = r[1];
                bh[2*np+1][0] = r[2]; bh[2*np+1][1] = r[3];
                ldm4(r, bBl + off);
                bl[2*np][0] = r[0]; bl[2*np][1] = r[1];
                bl[2*np+1][0] = r[2]; bl[2*np+1][1] = r[3];
            }
#pragma unroll
            for (int mt = 0; mt < 2; mt++)
#pragma unroll
                for (int nt = 0; nt < NT; nt++) {
                    mma_bf16(acc[mt][nt], ah[mt], bh[nt]);
                    mma_bf16(acc[mt][nt], ah[mt], bl[nt]);
                    mma_bf16(acc[mt][nt], al[mt], bh[nt]);
                }
        }
        __syncthreads();             // all reads done before stage reuse
    }

    // ---------- epilogue ----------
#pragma unroll
    for (int mt = 0; mt < 2; mt++) {
        const int gm = blockIdx.y * 128 + m0w + mt * 16 + (lane >> 2);
#pragma unroll
        for (int nt = 0; nt < NT; nt++) {
            const int gn = blockIdx.x * BN + n0w + nt * 8 + ((lane & 3) << 1);
            const size_t o0 = (size_t)gm * ldn + gn;
            const size_t o1 = (size_t)(gm + 8) * ldn + gn;
            if (MODE == 0) {
                float2 bv = *(const float2*)(bias + gn);
                float2 r0, r1;
                r0.x = acc[mt][nt][0] + bv.x;  r0.y = acc[mt][nt][1] + bv.y;
                r1.x = acc[mt][nt][2] + bv.x;  r1.y = acc[mt][nt][3] + bv.y;
                *(float2*)(C + o0) = r0;
                *(float2*)(C + o1) = r1;
            } else if (MODE == 1) {
                float2 d0 = *(const float2*)(Dm + o0);
                float2 d1 = *(const float2*)(Dm + o1);
                float t0 = tanhf(acc[mt][nt][0] + d0.x);
                float t1 = tanhf(acc[mt][nt][1] + d0.y);
                float t2 = tanhf(acc[mt][nt][2] + d1.x);
                float t3 = tanhf(acc[mt][nt][3] + d1.y);
                __nv_bfloat162 h0 = split_hi(t0, t1);
                __nv_bfloat162 h1 = split_hi(t2, t3);
                *(__nv_bfloat162*)(Chp + o0) = h0;
                *(__nv_bfloat162*)(Chp + o1) = h1;
                *(__nv_bfloat162*)(Clp + o0) = split_lo(t0, t1, h0);
                *(__nv_bfloat162*)(Clp + o1) = split_lo(t2, t3, h1);
            } else {
                // MODE 2: f = acc + bias; fused upd_simple (C holds z in/out)
                float2 bv = *(const float2*)(bias + gn);
                float f0 = acc[mt][nt][0] + bv.x;
                float f1 = acc[mt][nt][1] + bv.y;
                float f2 = acc[mt][nt][2] + bv.x;
                float f3 = acc[mt][nt][3] + bv.y;
                float2 z0 = *(const float2*)(C + o0);
                float2 z1 = *(const float2*)(C + o1);
                float2 gg0 = { f0 - z0.x, f1 - z0.y };
                float2 gg1 = { f2 - z1.x, f3 - z1.y };
                *(float2*)(Ghs + o0) = gg0;
                *(float2*)(Ghs + o1) = gg1;
                *(float2*)(Zhs + o0) = z0;
                *(float2*)(Zhs + o1) = z1;
                float2 w0 = { f0, f1 }, w1 = { f2, f3 };
                *(float2*)(C + o0) = w0;
                *(float2*)(C + o1) = w1;
                __nv_bfloat162 h0 = split_hi(f0, f1);
                __nv_bfloat162 h1 = split_hi(f2, f3);
                *(__nv_bfloat162*)(Chp + o0) = h0;
                *(__nv_bfloat162*)(Chp + o1) = h1;
                *(__nv_bfloat162*)(Clp + o0) = split_lo(f0, f1, h0);
                *(__nv_bfloat162*)(Clp + o1) = split_lo(f2, f3, h1);
            }
        }
    }
}

// ---------------- one-time converters ----------------
__global__ void conv_wT(const float* __restrict__ W,
                        __nv_bfloat16* __restrict__ Th, __nv_bfloat16* __restrict__ Tl,
                        int K, int N)
{
    __shared__ float t[32][33];
    int n0 = blockIdx.x * 32, k0 = blockIdx.y * 32;
    int tx = threadIdx.x, ty = threadIdx.y;   // 32 x 8
#pragma unroll
    for (int r = 0; r < 32; r += 8)
        t[ty + r][tx] = W[(size_t)(k0 + ty + r) * N + n0 + tx];
    __syncthreads();
#pragma unroll
    for (int r = 0; r < 32; r += 8) {
        float v = t[tx][ty + r];
        __nv_bfloat16 hb = __float2bfloat16(v);
        size_t o = (size_t)(n0 + ty + r) * K + k0 + tx;
        Th[o] = hb;
        Tl[o] = __float2bfloat16(v - __bfloat162float(hb));
    }
}
__global__ void conv_plane(const float* __restrict__ X,
                           __nv_bfloat16* __restrict__ Xh, __nv_bfloat16* __restrict__ Xl)
{
    int i = blockIdx.x * blockDim.x + threadIdx.x;
    float4 v = ((const float4*)X)[i];
    __nv_bfloat162 h01 = split_hi(v.x, v.y), h23 = split_hi(v.z, v.w);
    ((__nv_bfloat162*)Xh)[i*2]   = h01;
    ((__nv_bfloat162*)Xh)[i*2+1] = h23;
    ((__nv_bfloat162*)Xl)[i*2]   = split_lo(v.x, v.y, h01);
    ((__nv_bfloat162*)Xl)[i*2+1] = split_lo(v.z, v.w, h23);
}

// ---------------- iteration 0: h = tanh(xb) ----------------
__global__ void tanh_map(const float* __restrict__ src,
                         __nv_bfloat16* __restrict__ Hh, __nv_bfloat16* __restrict__ Hl)
{
    int i = blockIdx.x * blockDim.x + threadIdx.x;
    float4 v = ((const float4*)src)[i];
    v.x = tanhf(v.x); v.y = tanhf(v.y); v.z = tanhf(v.z); v.w = tanhf(v.w);
    __nv_bfloat162 h01 = split_hi(v.x, v.y), h23 = split_hi(v.z, v.w);
    ((__nv_bfloat162*)Hh)[i*2]   = h01;
    ((__nv_bfloat162*)Hh)[i*2+1] = h23;
    ((__nv_bfloat162*)Hl)[i*2]   = split_lo(v.x, v.y, h01);
    ((__nv_bfloat162*)Hl)[i*2+1] = split_lo(v.z, v.w, h23);
}

// ---------------- Anderson: HTH/HTy reduction ----------------
__global__ void reduce_k(const float* __restrict__ f, const float* __restrict__ z,
                         int s1, int s2, int s3, int s4)
{
    int b = blockIdx.y;
    int base = b * (FLAT / 4);
    const float4* fp = (const float4*)f + base;
    const float4* zp = (const float4*)z + base;
    const float4* h1 = (const float4*)g_Gh[s1] + base;
    const float4* h2 = (const float4*)g_Gh[s2] + base;
    const float4* h3 = (const float4*)g_Gh[s3] + base;
    const float4* h4 = (const float4*)g_Gh[s4] + base;

    float acc[14];
#pragma unroll
    for (int v = 0; v < 14; v++) acc[v] = 0.f;

    int n4 = FLAT / 4;
    for (int i = blockIdx.x * blockDim.x + threadIdx.x; i < n4;
         i += gridDim.x * blockDim.x) {
        float4 fv = fp[i], zv = zp[i];
        float4 a1 = h1[i], a2 = h2[i], a3 = h3[i], a4 = h4[i];
        const float* fa = (const float*)&fv; const float* za = (const float*)&zv;
        const float* p1 = (const float*)&a1; const float* p2 = (const float*)&a2;
        const float* p3 = (const float*)&a3; const float* p4 = (const float*)&a4;
#pragma unroll
        for (int c = 0; c < 4; c++) {
            float g  = fa[c] - za[c];
            float d0 = g - p1[c];
            float d1 = g - p2[c];
            float d2 = g - p3[c];
            float d3 = g - p4[c];
            acc[0] += d0 * d0; acc[1] += d0 * d1; acc[2] += d0 * d2; acc[3] += d0 * d3;
            acc[4] += d1 * d1; acc[5] += d1 * d2; acc[6] += d1 * d3;
            acc[7] += d2 * d2; acc[8] += d2 * d3; acc[9] += d3 * d3;
            acc[10] += d0 * g; acc[11] += d1 * g; acc[12] += d2 * g; acc[13] += d3 * g;
        }
    }
#pragma unroll
    for (int v = 0; v < 14; v++)
#pragma unroll
        for (int o = 16; o > 0; o >>= 1)
            acc[v] += __shfl_down_sync(0xffffffffu, acc[v], o);

    __shared__ float sm[8][14];
    int w = threadIdx.x / 32, lane = threadIdx.x % 32;
    if (lane == 0) {
#pragma unroll
        for (int v = 0; v < 14; v++) sm[w][v] = acc[v];
    }
    __syncthreads();
    if (threadIdx.x < 14) {
        float s = 0.f;
#pragma unroll
        for (int w2 = 0; w2 < 8; w2++) s += sm[w2][threadIdx.x];
        atomicAdd(&g_red[b * 14 + threadIdx.x], s);
    }
}

// ---------------- 4x4 Schur-complement solve ----------------
__device__ __forceinline__ void inv2x2d(const float m[4], float o[4])
{
    float invDet = 1.f / (m[0] * m[3] - m[1] * m[2] + 1e-6f);
    o[0] =  m[3] * invDet; o[1] = -m[1] * invDet;
    o[2] = -m[2] * invDet; o[3] =  m[0] * invDet;
}
__device__ __forceinline__ void mul2x2d(const float a[4], const float b[4], float o[4])
{
    o[0] = a[0] * b[0] + a[1] * b[2]; o[1] = a[0] * b[1] + a[1] * b[3];
    o[2] = a[2] * b[0] + a[3] * b[2]; o[3] = a[2] * b[1] + a[3] * b[3];
}

__global__ void solve_k()
{
    int b = threadIdx.x;
    if (b >= 2) return;
    const float* r = &g_red[b * 14];
    float H[4][4];
    H[0][0] = r[0] + LAMv; H[0][1] = r[1];        H[0][2] = r[2];        H[0][3] = r[3];
    H[1][0] = r[1];        H[1][1] = r[4] + LAMv; H[1][2] = r[5];        H[1][3] = r[6];
    H[2][0] = r[2];        H[2][1] = r[5];        H[2][2] = r[7] + LAMv; H[2][3] = r[8];
    H[3][0] = r[3];        H[3][1] = r[6];        H[3][2] = r[8];        H[3][3] = r[9] + LAMv;
    float y[4] = { r[10], r[11], r[12], r[13] };

    float A_[4] = { H[0][0], H[0][1], H[1][0], H[1][1] };
    float Bb[4] = { H[0][2], H[0][3], H[1][2], H[1][3] };
    float C_[4] = { H[2][0], H[2][1], H[3][0], H[3][1] };
    float Dd[4] = { H[2][2], H[2][3], H[3][2], H[3][3] };

    float Ai[4];   inv2x2d(A_, Ai);
    float CAi[4];  mul2x2d(C_, Ai, CAi);
    float CAiB[4]; mul2x2d(CAi, Bb, CAiB);
    float Sch[4]  = { Dd[0] - CAiB[0], Dd[1] - CAiB[1], Dd[2] - CAiB[2], Dd[3] - CAiB[3] };
    float Si[4];   inv2x2d(Sch, Si);
    float SiCAi[4]; mul2x2d(Si, CAi, SiCAi);
    float AiB[4];   mul2x2d(Ai, Bb, AiB);
    float t11[4];   mul2x2d(AiB, SiCAi, t11);
    float b11[4] = { Ai[0] + t11[0], Ai[1] + t11[1], Ai[2] + t11[2], Ai[3] + t11[3] };
    float b12[4];   mul2x2d(AiB, Si, b12);
    b12[0] = -b12[0]; b12[1] = -b12[1]; b12[2] = -b12[2]; b12[3] = -b12[3];

    float inv[4][4] = {
        { b11[0],  b11[1],  b12[0],  b12[1] },
        { b11[2],  b11[3],  b12[2],  b12[3] },
        { -SiCAi[0], -SiCAi[1], Si[0], Si[1] },
        { -SiCAi[2], -SiCAi[3], Si[2], Si[3] }
    };
#pragma unroll
    for (int j = 0; j < 4; j++)
        g_gamma[b * 4 + j] = inv[j][0] * y[0] + inv[j][1] * y[1]
                           + inv[j][2] * y[2] + inv[j][3] * y[3];
}

// ---------------- Anderson mixed update (+ z planes) ----------------
__global__ void upd_anderson(const float* __restrict__ f, float* __restrict__ z,
                             float* __restrict__ dst,
                             int s1, int s2, int s3, int s4, int sw)
{
    int i = blockIdx.x * blockDim.x + threadIdx.x;
    int b = i >> 17;
    float ga0 = g_gamma[b * 4 + 0];
    float ga1 = g_gamma[b * 4 + 1];
    float ga2 = g_gamma[b * 4 + 2];
    float ga3 = g_gamma[b * 4 + 3];

    float4 fv = ((const float4*)f)[i];
    float4 zv = ((const float4*)z)[i];
    float4 G1 = ((const float4*)g_Gh[s1])[i];
    float4 G2 = ((const float4*)g_Gh[s2])[i];
    float4 G3 = ((const float4*)g_Gh[s3])[i];
    float4 G4 = ((const float4*)g_Gh[s4])[i];
    float4 Z1 = ((const float4*)g_Zh[s1])[i];
    float4 Z2 = ((const float4*)g_Zh[s2])[i];
    float4 Z3 = ((const float4*)g_Zh[s3])[i];
    float4 Z4 = ((const float4*)g_Zh[s4])[i];

    float4 gv, ov;
    float* fa = (float*)&fv;  float* za = (float*)&zv;
    float* g1 = (float*)&G1;  float* g2 = (float*)&G2;
    float* g3 = (float*)&G3;  float* g4 = (float*)&G4;
    float* z1 = (float*)&Z1;  float* z2 = (float*)&Z2;
    float* z3 = (float*)&Z3;  float* z4 = (float*)&Z4;
    float* gva = (float*)&gv; float* ova = (float*)&ov;

#pragma unroll
    for (int c = 0; c < 4; c++) {
        float zc = za[c];
        float g  = fa[c] - zc;
        float corr = ga0 * ((zc - z1[c]) + (g - g1[c]))
                   + ga1 * ((zc - z2[c]) + (g - g2[c]))
                   + ga2 * ((zc - z3[c]) + (g - g3[c]))
                   + ga3 * ((zc - z4[c]) + (g - g4[c]));
        gva[c] = g;
        ova[c] = zc + g - corr;
    }
    ((float4*)g_Gh[sw])[i] = gv;
    ((float4*)g_Zh[sw])[i] = zv;
    ((float4*)dst)[i] = ov;
    __nv_bfloat162 h01 = split_hi(ov.x, ov.y), h23 = split_hi(ov.z, ov.w);
    ((__nv_bfloat162*)g_zp[0])[i*2]   = h01;
    ((__nv_bfloat162*)g_zp[0])[i*2+1] = h23;
    ((__nv_bfloat162*)g_zp[1])[i*2]   = split_lo(ov.x, ov.y, h01);
    ((__nv_bfloat162*)g_zp[1])[i*2+1] = split_lo(ov.z, ov.w, h23);
}

// ---------------- launcher ----------------
extern "C" void kernel_launch(void* const* d_in, const int* in_sizes, int n_in,
                              void* d_out, int out_size)
{
    (void)in_sizes; (void)n_in; (void)out_size;
    const float* x  = (const float*)d_in[0];
    const float* W1 = (const float*)d_in[1];
    const float* Wx = (const float*)d_in[2];
    const float* b1 = (const float*)d_in[3];
    const float* W2 = (const float*)d_in[4];
    const float* b2 = (const float*)d_in[5];
    float* out = (float*)d_out;

    float *xb, *z, *f, *red, *Gh0, *Zh0;
    cudaGetSymbolAddress((void**)&xb,  g_xb);
    cudaGetSymbolAddress((void**)&z,   g_z);
    cudaGetSymbolAddress((void**)&f,   g_f);
    cudaGetSymbolAddress((void**)&red, g_red);
    cudaGetSymbolAddress((void**)&Gh0, g_Gh);
    cudaGetSymbolAddress((void**)&Zh0, g_Zh);
    __nv_bfloat16 *W1Th, *W1Tl, *WxTh, *WxTl, *W2Th, *W2Tl, *xh, *xl, *zh, *zl, *hh, *hl;
    cudaGetSymbolAddress((void**)&W1Th, g_W1T); W1Tl = W1Th + (size_t)Fq*Dq;
    cudaGetSymbolAddress((void**)&WxTh, g_WxT); WxTl = WxTh + (size_t)Fq*Dq;
    cudaGetSymbolAddress((void**)&W2Th, g_W2T); W2Tl = W2Th + (size_t)Dq*Fq;
    cudaGetSymbolAddress((void**)&xh,   g_xp);  xl   = xh   + TOT;
    cudaGetSymbolAddress((void**)&zh,   g_zp);  zl   = zh   + TOT;
    cudaGetSymbolAddress((void**)&hh,   g_hp);  hl   = hh   + (size_t)MF*Fq;

    const int DYN128 = 3 * (2*128*64*2 + 2*128*64*2) + 1024;   // 193 KB
    const int DYN64  = 3 * (2*128*64*2 + 2* 64*64*2) + 1024;   // 145 KB
    cudaFuncSetAttribute(gemm_p<128,0>, cudaFuncAttributeMaxDynamicSharedMemorySize, DYN128);
    cudaFuncSetAttribute(gemm_p<128,1>, cudaFuncAttributeMaxDynamicSharedMemorySize, DYN128);
    cudaFuncSetAttribute(gemm_p<64,0>,  cudaFuncAttributeMaxDynamicSharedMemorySize, DYN64);
    cudaFuncSetAttribute(gemm_p<64,2>,  cudaFuncAttributeMaxDynamicSharedMemorySize, DYN64);

    cudaMemsetAsync(z, 0, (size_t)TOT * sizeof(float));

    // one-time conversions
    dim3 tb(32, 8);
    conv_wT<<<dim3(Fq/32, Dq/32), tb>>>(W1, W1Th, W1Tl, Dq, Fq);
    conv_wT<<<dim3(Fq/32, Dq/32), tb>>>(Wx, WxTh, WxTl, Dq, Fq);
    conv_wT<<<dim3(Dq/32, Fq/32), tb>>>(W2, W2Th, W2Tl, Fq, Dq);
    conv_plane<<<TOT/4/256, 256>>>(x, xh, xl);

    dim3 g1(Fq / 128, MF / 128);   // 16 x 16
    dim3 g2(Dq / 64,  MF / 128);   // 8 x 16

    // xb = x @ Wx + b1
    gemm_p<128,0><<<g1, 256, DYN128>>>(xh, xl, WxTh, WxTl, b1, nullptr, xb,
                                       nullptr, nullptr, nullptr, nullptr, Dq, Fq);

    const int upd_blocks = TOT / 4 / 256;
    for (int i = 0; i < 12; i++) {
        // h = tanh(z @ W1 + xb)  -> bf16 hi/lo planes
        if (i == 0)
            tanh_map<<<(size_t)MF * Fq / 4 / 256, 256>>>(xb, hh, hl);
        else
            gemm_p<128,1><<<g1, 256, DYN128>>>(zh, zl, W1Th, W1Tl, nullptr, xb, nullptr,
                                               hh, hl, nullptr, nullptr, Dq, Fq);
        // f = h @ W2 + b2
        if (i < 5) {
            // fused: f, g-history, z-history, z_new, z planes
            gemm_p<64,2><<<g2, 256, DYN64>>>(hh, hl, W2Th, W2Tl, b2, nullptr, z,
                                             zh, zl, Gh0 + (size_t)(i & 3) * TOT,
                                             Zh0 + (size_t)(i & 3) * TOT, Fq, Dq);
        } else {
            gemm_p<64,0><<<g2, 256, DYN64>>>(hh, hl, W2Th, W2Tl, b2, nullptr, f,
                                             nullptr, nullptr, nullptr, nullptr, Fq, Dq);
            float* dst = (i == 11) ? out : z;
            cudaMemsetAsync(red, 0, 28 * sizeof(float));
            reduce_k<<<dim3(128, 2), 256>>>(f, z, (i - 1) & 3, (i - 2) & 3,
                                            (i - 3) & 3, (i - 4) & 3);
            solve_k<<<1, 32>>>();
            upd_anderson<<<upd_blocks, 256>>>(f, z, dst, (i - 1) & 3, (i - 2) & 3,
                                              (i - 3) & 3, (i - 4) & 3, i & 3);
        }
    }
}

// round 11
// speedup vs baseline: 1.1102x; 1.0064x over previous
#include <cuda_runtime.h>
#include <cuda_bf16.h>
#include <math.h>
#include <stdint.h>

// Problem constants
#define Bq   2
#define Sq   1024
#define Dq   512
#define Fq   2048
#define MF   (Bq*Sq)          // 2048 GEMM rows
#define FLAT (Sq*Dq)          // 524288 per-batch flat size (2^19)
#define TOT  (Bq*FLAT)        // 1048576
#define LAMv 1e-4f

// ---------------- scratch (no allocations allowed) ----------------
__device__ float g_xb[(size_t)MF*Fq];   // x@Wx + b1 (16MB)
__device__ float g_z [TOT];             // current z (fp32)
__device__ float g_f [TOT];             // f(z) (only used i>=5)
__device__ float g_Gh[4][TOT];          // g history, circular
__device__ float g_Zh[4][TOT];          // z history, circular
__device__ float g_red[2*14];
__device__ float g_gamma[2*4];

// bf16 hi/lo planes (error-compensated split operands)
__device__ __nv_bfloat16 g_W1T[2][(size_t)Fq*Dq];  // [N=2048][K=512]
__device__ __nv_bfloat16 g_WxT[2][(size_t)Fq*Dq];
__device__ __nv_bfloat16 g_W2T[2][(size_t)Dq*Fq];  // [512][2048]
__device__ __nv_bfloat16 g_xp [2][TOT];
__device__ __nv_bfloat16 g_zp [2][TOT];
__device__ __nv_bfloat16 g_hp [2][(size_t)MF*Fq];

// ======================= helpers =======================
__device__ __forceinline__ uint32_t smem_u32(const void* p){
    uint32_t a;
    asm("{ .reg .u64 t; cvta.to.shared.u64 t, %1; cvt.u32.u64 %0, t; }" : "=r"(a) : "l"(p));
    return a;
}
#define SWZ(o) ((o) ^ (((o) >> 3) & 0x70))

__device__ __forceinline__ void ldm4(uint32_t* r, uint32_t addr){
    asm volatile("ldmatrix.sync.aligned.m8n8.x4.shared.b16 {%0,%1,%2,%3}, [%4];"
        : "=r"(r[0]), "=r"(r[1]), "=r"(r[2]), "=r"(r[3]) : "r"(addr));
}
__device__ __forceinline__ void mma_bf16(float* c, const uint32_t* a, const uint32_t* b){
    asm volatile("mma.sync.aligned.m16n8k16.row.col.f32.bf16.bf16.f32 "
        "{%0,%1,%2,%3}, {%4,%5,%6,%7}, {%8,%9}, {%0,%1,%2,%3};"
        : "+f"(c[0]), "+f"(c[1]), "+f"(c[2]), "+f"(c[3])
        : "r"(a[0]), "r"(a[1]), "r"(a[2]), "r"(a[3]), "r"(b[0]), "r"(b[1]));
}
__device__ __forceinline__ void cpasync16(uint32_t dst, const void* src){
    asm volatile("cp.async.cg.shared.global [%0], [%1], 16;" :: "r"(dst), "l"(src));
}
__device__ __forceinline__ void cpcommit(){ asm volatile("cp.async.commit_group;" ::: "memory"); }
template<int N> __device__ __forceinline__ void cpwait(){
    asm volatile("cp.async.wait_group %0;" :: "n"(N) : "memory");
}
__device__ __forceinline__ __nv_bfloat162 split_hi(float a, float b){
    return __floats2bfloat162_rn(a, b);
}
__device__ __forceinline__ __nv_bfloat162 split_lo(float a, float b, __nv_bfloat162 h){
    return __floats2bfloat162_rn(a - __bfloat162float(h.x), b - __bfloat162float(h.y));
}

// ---------------- 4x4 Schur-complement solve (device, replicates reference) ----------------
__device__ __forceinline__ void inv2x2d(const float m[4], float o[4])
{
    float invDet = 1.f / (m[0] * m[3] - m[1] * m[2] + 1e-6f);
    o[0] =  m[3] * invDet; o[1] = -m[1] * invDet;
    o[2] = -m[2] * invDet; o[3] =  m[0] * invDet;
}
__device__ __forceinline__ void mul2x2d(const float a[4], const float b[4], float o[4])
{
    o[0] = a[0] * b[0] + a[1] * b[2]; o[1] = a[0] * b[1] + a[1] * b[3];
    o[2] = a[2] * b[0] + a[3] * b[2]; o[3] = a[2] * b[1] + a[3] * b[3];
}
__device__ void solve_gamma(const float* r, float* gam)
{
    float H[4][4];
    H[0][0] = r[0] + LAMv; H[0][1] = r[1];        H[0][2] = r[2];        H[0][3] = r[3];
    H[1][0] = r[1];        H[1][1] = r[4] + LAMv; H[1][2] = r[5];        H[1][3] = r[6];
    H[2][0] = r[2];        H[2][1] = r[5];        H[2][2] = r[7] + LAMv; H[2][3] = r[8];
    H[3][0] = r[3];        H[3][1] = r[6];        H[3][2] = r[8];        H[3][3] = r[9] + LAMv;
    float y[4] = { r[10], r[11], r[12], r[13] };

    float A_[4] = { H[0][0], H[0][1], H[1][0], H[1][1] };
    float Bb[4] = { H[0][2], H[0][3], H[1][2], H[1][3] };
    float C_[4] = { H[2][0], H[2][1], H[3][0], H[3][1] };
    float Dd[4] = { H[2][2], H[2][3], H[3][2], H[3][3] };

    float Ai[4];   inv2x2d(A_, Ai);
    float CAi[4];  mul2x2d(C_, Ai, CAi);
    float CAiB[4]; mul2x2d(CAi, Bb, CAiB);
    float Sch[4]  = { Dd[0] - CAiB[0], Dd[1] - CAiB[1], Dd[2] - CAiB[2], Dd[3] - CAiB[3] };
    float Si[4];   inv2x2d(Sch, Si);
    float SiCAi[4]; mul2x2d(Si, CAi, SiCAi);
    float AiB[4];   mul2x2d(Ai, Bb, AiB);
    float t11[4];   mul2x2d(AiB, SiCAi, t11);
    float b11[4] = { Ai[0] + t11[0], Ai[1] + t11[1], Ai[2] + t11[2], Ai[3] + t11[3] };
    float b12[4];   mul2x2d(AiB, Si, b12);
    b12[0] = -b12[0]; b12[1] = -b12[1]; b12[2] = -b12[2]; b12[3] = -b12[3];

    float inv[4][4] = {
        { b11[0],  b11[1],  b12[0],  b12[1] },
        { b11[2],  b11[3],  b12[2],  b12[3] },
        { -SiCAi[0], -SiCAi[1], Si[0], Si[1] },
        { -SiCAi[2], -SiCAi[3], Si[2], Si[3] }
    };
#pragma unroll
    for (int j = 0; j < 4; j++)
        gam[j] = inv[j][0] * y[0] + inv[j][1] * y[1]
               + inv[j][2] * y[2] + inv[j][3] * y[3];
}

// ======================= pipelined split-bf16 mma.sync GEMM =======================
// R5-proven geometry: CTA tile 128(M) x BN, K-slab 64, SW128, 3-stage cp.async.
// MODE 0: C fp32 = acc + bias[n]
// MODE 1: t = tanh(acc + Dm[m][n]); write Chp/Clp bf16 hi/lo planes
// MODE 2: f = acc + bias[n]; fused upd_simple (C holds z in/out)
// MODE 3: f = acc + bias[n]; C=f; fused reduce_k partials (Dm holds z input;
//         histories g_Gh[s1..s4]; atomicAdd 14 sums into g_red)
template<int BN, int MODE>
__global__ __launch_bounds__(256, 1) void gemm_p(
    const __nv_bfloat16* __restrict__ Ahp, const __nv_bfloat16* __restrict__ Alp,
    const __nv_bfloat16* __restrict__ Bhp, const __nv_bfloat16* __restrict__ Blp,
    const float* __restrict__ bias, const float* __restrict__ Dm,
    float* __restrict__ C,
    __nv_bfloat16* __restrict__ Chp, __nv_bfloat16* __restrict__ Clp,
    float* __restrict__ Ghs, float* __restrict__ Zhs,
    int K, int ldn, int s1, int s2, int s3, int s4)
{
    constexpr int ASTG = 128 * 64 * 2;         // one A plane per stage (16 KB)
    constexpr int BSTG = BN  * 64 * 2;         // one B plane per stage
    constexpr int STG  = 2 * ASTG + 2 * BSTG;  // stage size
    constexpr int BIT  = (BN * 8) / 256;       // B chunks per thread per plane
    constexpr int NT   = BN / 16;              // n8-tiles per warp

    extern __shared__ char dynraw[];
    char* dyn = (char*)(((uintptr_t)dynraw + 1023) & ~(uintptr_t)1023);

    const int tid  = threadIdx.x;
    const int wid  = tid >> 5;
    const int lane = tid & 31;
    const int m0w  = (wid & 3) * 32;
    const int n0w  = (wid >> 2) * (BN / 2);
    const int NS   = K >> 6;

    float acc[2][NT][4];
#pragma unroll
    for (int mt = 0; mt < 2; mt++)
#pragma unroll
        for (int nt = 0; nt < NT; nt++)
#pragma unroll
            for (int v = 0; v < 4; v++) acc[mt][nt][v] = 0.f;

    auto issue = [&](int s, int st){
        char* buf = dyn + st * STG;
        uint32_t ba = smem_u32(buf);
        const __nv_bfloat16* ap[2] = { Ahp, Alp };
#pragma unroll
        for (int p = 0; p < 2; p++)
#pragma unroll
            for (int it = 0; it < 4; it++) {
                int c = tid + it * 256;          // 0..1023
                int row = c >> 3, kc = c & 7;
                const void* src = ap[p] + (size_t)(blockIdx.y * 128 + row) * K + s * 64 + kc * 8;
                cpasync16(ba + p * ASTG + SWZ((uint32_t)(row * 128 + kc * 16)), src);
            }
        const __nv_bfloat16* bp[2] = { Bhp, Blp };
#pragma unroll
        for (int p = 0; p < 2; p++)
#pragma unroll
            for (int it = 0; it < BIT; it++) {
                int c = tid + it * 256;
                int row = c >> 3, kc = c & 7;
                const void* src = bp[p] + (size_t)(blockIdx.x * BN + row) * K + s * 64 + kc * 8;
                cpasync16(ba + 2 * ASTG + p * BSTG + SWZ((uint32_t)(row * 128 + kc * 16)), src);
            }
    };

    issue(0, 0); cpcommit();
    issue(1, 1); cpcommit();

    const int arow = lane & 15;
    const int brow = (lane & 7) | ((lane >> 1) & 8);
    const int asel = lane >> 4;
    const int bsel = (lane >> 3) & 1;

    for (int s = 0; s < NS; s++) {
        const int st = s % 3;
        if (s + 2 < NS) issue(s + 2, (s + 2) % 3);
        cpcommit();
        cpwait<2>();
        __syncthreads();

        const uint32_t bAh = smem_u32(dyn + st * STG);
        const uint32_t bAl = bAh + ASTG;
        const uint32_t bBh = bAh + 2 * ASTG;
        const uint32_t bBl = bBh + BSTG;

#pragma unroll
        for (int ks = 0; ks < 4; ks++) {
            uint32_t ah[2][4], al[2][4];
            const int achunk = (ks << 1) + asel;
#pragma unroll
            for (int mt = 0; mt < 2; mt++) {
                uint32_t off = SWZ((uint32_t)((m0w + mt * 16 + arow) * 128 + achunk * 16));
                ldm4(ah[mt], bAh + off);
                ldm4(al[mt], bAl + off);
            }
            uint32_t bh[NT][2], bl[NT][2];
            const int bchunk = (ks << 1) + bsel;
#pragma unroll
            for (int np = 0; np < NT / 2; np++) {
                uint32_t off = SWZ((uint32_t)((n0w + np * 16 + brow) * 128 + bchunk * 16));
                uint32_t r[4];
                ldm4(r, bBh + off);
                bh[2*np][0] = r[0]; bh[2*np][1] = r[1];
                bh[2*np+1][0] = r[2]; bh[2*np+1][1] = r[3];
                ldm4(r, bBl + off);
                bl[2*np][0] = r[0]; bl[2*np][1] = r[1];
                bl[2*np+1][0] = r[2]; bl[2*np+1][1] = r[3];
            }
            // term-outermost: 2*NT independent HMMAs between accumulator reuses
#pragma unroll
            for (int mt = 0; mt < 2; mt++)
#pragma unroll
                for (int nt = 0; nt < NT; nt++)
                    mma_bf16(acc[mt][nt], ah[mt], bh[nt]);
#pragma unroll
            for (int mt = 0; mt < 2; mt++)
#pragma unroll
                for (int nt = 0; nt < NT; nt++)
                    mma_bf16(acc[mt][nt], ah[mt], bl[nt]);
#pragma unroll
            for (int mt = 0; mt < 2; mt++)
#pragma unroll
                for (int nt = 0; nt < NT; nt++)
                    mma_bf16(acc[mt][nt], al[mt], bh[nt]);
        }
        __syncthreads();
    }

    // ---------- epilogue ----------
    float part[14];
    if (MODE == 3) {
#pragma unroll
        for (int v = 0; v < 14; v++) part[v] = 0.f;
    }
#pragma unroll
    for (int mt = 0; mt < 2; mt++) {
        const int gm = blockIdx.y * 128 + m0w + mt * 16 + (lane >> 2);
#pragma unroll
        for (int nt = 0; nt < NT; nt++) {
            const int gn = blockIdx.x * BN + n0w + nt * 8 + ((lane & 3) << 1);
            const size_t o0 = (size_t)gm * ldn + gn;
            const size_t o1 = (size_t)(gm + 8) * ldn + gn;
            if (MODE == 0) {
                float2 bv = *(const float2*)(bias + gn);
                float2 r0, r1;
                r0.x = acc[mt][nt][0] + bv.x;  r0.y = acc[mt][nt][1] + bv.y;
                r1.x = acc[mt][nt][2] + bv.x;  r1.y = acc[mt][nt][3] + bv.y;
                *(float2*)(C + o0) = r0;
                *(float2*)(C + o1) = r1;
            } else if (MODE == 1) {
                float2 d0 = *(const float2*)(Dm + o0);
                float2 d1 = *(const float2*)(Dm + o1);
                float t0 = tanhf(acc[mt][nt][0] + d0.x);
                float t1 = tanhf(acc[mt][nt][1] + d0.y);
                float t2 = tanhf(acc[mt][nt][2] + d1.x);
                float t3 = tanhf(acc[mt][nt][3] + d1.y);
                __nv_bfloat162 h0 = split_hi(t0, t1);
                __nv_bfloat162 h1 = split_hi(t2, t3);
                *(__nv_bfloat162*)(Chp + o0) = h0;
                *(__nv_bfloat162*)(Chp + o1) = h1;
                *(__nv_bfloat162*)(Clp + o0) = split_lo(t0, t1, h0);
                *(__nv_bfloat162*)(Clp + o1) = split_lo(t2, t3, h1);
            } else if (MODE == 2) {
                float2 bv = *(const float2*)(bias + gn);
                float f0 = acc[mt][nt][0] + bv.x;
                float f1 = acc[mt][nt][1] + bv.y;
                float f2 = acc[mt][nt][2] + bv.x;
                float f3 = acc[mt][nt][3] + bv.y;
                float2 z0 = *(const float2*)(C + o0);
                float2 z1 = *(const float2*)(C + o1);
                float2 gg0 = { f0 - z0.x, f1 - z0.y };
                float2 gg1 = { f2 - z1.x, f3 - z1.y };
                *(float2*)(Ghs + o0) = gg0;
                *(float2*)(Ghs + o1) = gg1;
                *(float2*)(Zhs + o0) = z0;
                *(float2*)(Zhs + o1) = z1;
                float2 w0 = { f0, f1 }, w1 = { f2, f3 };
                *(float2*)(C + o0) = w0;
                *(float2*)(C + o1) = w1;
                __nv_bfloat162 h0 = split_hi(f0, f1);
                __nv_bfloat162 h1 = split_hi(f2, f3);
                *(__nv_bfloat162*)(Chp + o0) = h0;
                *(__nv_bfloat162*)(Chp + o1) = h1;
                *(__nv_bfloat162*)(Clp + o0) = split_lo(f0, f1, h0);
                *(__nv_bfloat162*)(Clp + o1) = split_lo(f2, f3, h1);
            } else {
                // MODE 3: f = acc + bias; write f; accumulate reduce partials
                float2 bv = *(const float2*)(bias + gn);
                float fr[4];
                fr[0] = acc[mt][nt][0] + bv.x;
                fr[1] = acc[mt][nt][1] + bv.y;
                fr[2] = acc[mt][nt][2] + bv.x;
                fr[3] = acc[mt][nt][3] + bv.y;
                *(float2*)(C + o0) = *(float2*)&fr[0];
                *(float2*)(C + o1) = *(float2*)&fr[2];
                float2 z0 = *(const float2*)(Dm + o0);
                float2 z1 = *(const float2*)(Dm + o1);
                float gg[4] = { fr[0] - z0.x, fr[1] - z0.y, fr[2] - z1.x, fr[3] - z1.y };
                float2 h1a = *(const float2*)(&g_Gh[s1][0] + o0);
                float2 h1b = *(const float2*)(&g_Gh[s1][0] + o1);
                float2 h2a = *(const float2*)(&g_Gh[s2][0] + o0);
                float2 h2b = *(const float2*)(&g_Gh[s2][0] + o1);
                float2 h3a = *(const float2*)(&g_Gh[s3][0] + o0);
                float2 h3b = *(const float2*)(&g_Gh[s3][0] + o1);
                float2 h4a = *(const float2*)(&g_Gh[s4][0] + o0);
                float2 h4b = *(const float2*)(&g_Gh[s4][0] + o1);
                float hv[4][4] = {
                    { h1a.x, h1a.y, h1b.x, h1b.y },
                    { h2a.x, h2a.y, h2b.x, h2b.y },
                    { h3a.x, h3a.y, h3b.x, h3b.y },
                    { h4a.x, h4a.y, h4b.x, h4b.y }
                };
#pragma unroll
                for (int e = 0; e < 4; e++) {
                    float g  = gg[e];
                    float d0 = g - hv[0][e];
                    float d1 = g - hv[1][e];
                    float d2 = g - hv[2][e];
                    float d3 = g - hv[3][e];
                    part[0] += d0 * d0; part[1] += d0 * d1; part[2] += d0 * d2; part[3] += d0 * d3;
                    part[4] += d1 * d1; part[5] += d1 * d2; part[6] += d1 * d3;
                    part[7] += d2 * d2; part[8] += d2 * d3; part[9] += d3 * d3;
                    part[10] += d0 * g; part[11] += d1 * g; part[12] += d2 * g; part[13] += d3 * g;
                }
            }
        }
    }

    if (MODE == 3) {
        __shared__ float sred[8][14];
#pragma unroll
        for (int v = 0; v < 14; v++)
#pragma unroll
            for (int o = 16; o > 0; o >>= 1)
                part[v] += __shfl_down_sync(0xffffffffu, part[v], o);
        if (lane == 0) {
#pragma unroll
            for (int v = 0; v < 14; v++) sred[wid][v] = part[v];
        }
        __syncthreads();
        if (tid < 14) {
            float ssum = 0.f;
#pragma unroll
            for (int w = 0; w < 8; w++) ssum += sred[w][tid];
            int batch = blockIdx.y >> 3;   // 128 rows/block, 1024 rows/batch
            atomicAdd(&g_red[batch * 14 + tid], ssum);
        }
    }
}

// ---------------- one-time converters ----------------
__global__ void conv_wT(const float* __restrict__ W,
                        __nv_bfloat16* __restrict__ Th, __nv_bfloat16* __restrict__ Tl,
                        int K, int N)
{
    __shared__ float t[32][33];
    int n0 = blockIdx.x * 32, k0 = blockIdx.y * 32;
    int tx = threadIdx.x, ty = threadIdx.y;   // 32 x 8
#pragma unroll
    for (int r = 0; r < 32; r += 8)
        t[ty + r][tx] = W[(size_t)(k0 + ty + r) * N + n0 + tx];
    __syncthreads();
#pragma unroll
    for (int r = 0; r < 32; r += 8) {
        float v = t[tx][ty + r];
        __nv_bfloat16 hb = __float2bfloat16(v);
        size_t o = (size_t)(n0 + ty + r) * K + k0 + tx;
        Th[o] = hb;
        Tl[o] = __float2bfloat16(v - __bfloat162float(hb));
    }
}
__global__ void conv_plane(const float* __restrict__ X,
                           __nv_bfloat16* __restrict__ Xh, __nv_bfloat16* __restrict__ Xl)
{
    int i = blockIdx.x * blockDim.x + threadIdx.x;
    float4 v = ((const float4*)X)[i];
    __nv_bfloat162 h01 = split_hi(v.x, v.y), h23 = split_hi(v.z, v.w);
    ((__nv_bfloat162*)Xh)[i*2]   = h01;
    ((__nv_bfloat162*)Xh)[i*2+1] = h23;
    ((__nv_bfloat162*)Xl)[i*2]   = split_lo(v.x, v.y, h01);
    ((__nv_bfloat162*)Xl)[i*2+1] = split_lo(v.z, v.w, h23);
}

// ---------------- iteration 0: h = tanh(xb) ----------------
__global__ void tanh_map(const float* __restrict__ src,
                         __nv_bfloat16* __restrict__ Hh, __nv_bfloat16* __restrict__ Hl)
{
    int i = blockIdx.x * blockDim.x + threadIdx.x;
    float4 v = ((const float4*)src)[i];
    v.x = tanhf(v.x); v.y = tanhf(v.y); v.z = tanhf(v.z); v.w = tanhf(v.w);
    __nv_bfloat162 h01 = split_hi(v.x, v.y), h23 = split_hi(v.z, v.w);
    ((__nv_bfloat162*)Hh)[i*2]   = h01;
    ((__nv_bfloat162*)Hh)[i*2+1] = h23;
    ((__nv_bfloat162*)Hl)[i*2]   = split_lo(v.x, v.y, h01);
    ((__nv_bfloat162*)Hl)[i*2+1] = split_lo(v.z, v.w, h23);
}

// ---------------- Anderson mixed update (fused gamma solve, + z planes) ----------------
__global__ void upd_anderson(const float* __restrict__ f, float* __restrict__ z,
                             float* __restrict__ dst,
                             int s1, int s2, int s3, int s4, int sw)
{
    __shared__ float sg[8];
    if (threadIdx.x < 2)
        solve_gamma(&g_red[threadIdx.x * 14], &sg[threadIdx.x * 4]);
    __syncthreads();

    int i = blockIdx.x * blockDim.x + threadIdx.x;
    int b = i >> 17;
    float ga0 = sg[b * 4 + 0];
    float ga1 = sg[b * 4 + 1];
    float ga2 = sg[b * 4 + 2];
    float ga3 = sg[b * 4 + 3];

    float4 fv = ((const float4*)f)[i];
    float4 zv = ((const float4*)z)[i];
    float4 G1 = ((const float4*)g_Gh[s1])[i];
    float4 G2 = ((const float4*)g_Gh[s2])[i];
    float4 G3 = ((const float4*)g_Gh[s3])[i];
    float4 G4 = ((const float4*)g_Gh[s4])[i];
    float4 Z1 = ((const float4*)g_Zh[s1])[i];
    float4 Z2 = ((const float4*)g_Zh[s2])[i];
    float4 Z3 = ((const float4*)g_Zh[s3])[i];
    float4 Z4 = ((const float4*)g_Zh[s4])[i];

    float4 gv, ov;
    float* fa = (float*)&fv;  float* za = (float*)&zv;
    float* g1 = (float*)&G1;  float* g2 = (float*)&G2;
    float* g3 = (float*)&G3;  float* g4 = (float*)&G4;
    float* z1 = (float*)&Z1;  float* z2 = (float*)&Z2;
    float* z3 = (float*)&Z3;  float* z4 = (float*)&Z4;
    float* gva = (float*)&gv; float* ova = (float*)&ov;

#pragma unroll
    for (int c = 0; c < 4; c++) {
        float zc = za[c];
        float g  = fa[c] - zc;
        float corr = ga0 * ((zc - z1[c]) + (g - g1[c]))
                   + ga1 * ((zc - z2[c]) + (g - g2[c]))
                   + ga2 * ((zc - z3[c]) + (g - g3[c]))
                   + ga3 * ((zc - z4[c]) + (g - g4[c]));
        gva[c] = g;
        ova[c] = zc + g - corr;
    }
    ((float4*)g_Gh[sw])[i] = gv;
    ((float4*)g_Zh[sw])[i] = zv;
    ((float4*)dst)[i] = ov;
    __nv_bfloat162 h01 = split_hi(ov.x, ov.y), h23 = split_hi(ov.z, ov.w);
    ((__nv_bfloat162*)g_zp[0])[i*2]   = h01;
    ((__nv_bfloat162*)g_zp[0])[i*2+1] = h23;
    ((__nv_bfloat162*)g_zp[1])[i*2]   = split_lo(ov.x, ov.y, h01);
    ((__nv_bfloat162*)g_zp[1])[i*2+1] = split_lo(ov.z, ov.w, h23);
}

// ---------------- launcher ----------------
extern "C" void kernel_launch(void* const* d_in, const int* in_sizes, int n_in,
                              void* d_out, int out_size)
{
    (void)in_sizes; (void)n_in; (void)out_size;
    const float* x  = (const float*)d_in[0];
    const float* W1 = (const float*)d_in[1];
    const float* Wx = (const float*)d_in[2];
    const float* b1 = (const float*)d_in[3];
    const float* W2 = (const float*)d_in[4];
    const float* b2 = (const float*)d_in[5];
    float* out = (float*)d_out;

    float *xb, *z, *f, *red, *Gh0, *Zh0;
    cudaGetSymbolAddress((void**)&xb,  g_xb);
    cudaGetSymbolAddress((void**)&z,   g_z);
    cudaGetSymbolAddress((void**)&f,   g_f);
    cudaGetSymbolAddress((void**)&red, g_red);
    cudaGetSymbolAddress((void**)&Gh0, g_Gh);
    cudaGetSymbolAddress((void**)&Zh0, g_Zh);
    __nv_bfloat16 *W1Th, *W1Tl, *WxTh, *WxTl, *W2Th, *W2Tl, *xh, *xl, *zh, *zl, *hh, *hl;
    cudaGetSymbolAddress((void**)&W1Th, g_W1T); W1Tl = W1Th + (size_t)Fq*Dq;
    cudaGetSymbolAddress((void**)&WxTh, g_WxT); WxTl = WxTh + (size_t)Fq*Dq;
    cudaGetSymbolAddress((void**)&W2Th, g_W2T); W2Tl = W2Th + (size_t)Dq*Fq;
    cudaGetSymbolAddress((void**)&xh,   g_xp);  xl   = xh   + TOT;
    cudaGetSymbolAddress((void**)&zh,   g_zp);  zl   = zh   + TOT;
    cudaGetSymbolAddress((void**)&hh,   g_hp);  hl   = hh   + (size_t)MF*Fq;

    const int DYN128 = 3 * (2*128*64*2 + 2*128*64*2) + 1024;   // 193 KB
    const int DYN64  = 3 * (2*128*64*2 + 2* 64*64*2) + 1024;   // 145 KB
    cudaFuncSetAttribute(gemm_p<128,0>, cudaFuncAttributeMaxDynamicSharedMemorySize, DYN128);
    cudaFuncSetAttribute(gemm_p<128,1>, cudaFuncAttributeMaxDynamicSharedMemorySize, DYN128);
    cudaFuncSetAttribute(gemm_p<64,0>,  cudaFuncAttributeMaxDynamicSharedMemorySize, DYN64);
    cudaFuncSetAttribute(gemm_p<64,2>,  cudaFuncAttributeMaxDynamicSharedMemorySize, DYN64);
    cudaFuncSetAttribute(gemm_p<64,3>,  cudaFuncAttributeMaxDynamicSharedMemorySize, DYN64);

    cudaMemsetAsync(z, 0, (size_t)TOT * sizeof(float));

    // one-time conversions
    dim3 tb(32, 8);
    conv_wT<<<dim3(Fq/32, Dq/32), tb>>>(W1, W1Th, W1Tl, Dq, Fq);
    conv_wT<<<dim3(Fq/32, Dq/32), tb>>>(Wx, WxTh, WxTl, Dq, Fq);
    conv_wT<<<dim3(Dq/32, Fq/32), tb>>>(W2, W2Th, W2Tl, Fq, Dq);
    conv_plane<<<TOT/4/256, 256>>>(x, xh, xl);

    dim3 g1(Fq / 128, MF / 128);   // 16 x 16
    dim3 g2(Dq / 64,  MF / 128);   // 8 x 16

    // xb = x @ Wx + b1
    gemm_p<128,0><<<g1, 256, DYN128>>>(xh, xl, WxTh, WxTl, b1, nullptr, xb,
                                       nullptr, nullptr, nullptr, nullptr, Dq, Fq, 0,0,0,0);

    const int upd_blocks = TOT / 4 / 256;
    for (int i = 0; i < 12; i++) {
        // h = tanh(z @ W1 + xb)  -> bf16 hi/lo planes
        if (i == 0)
            tanh_map<<<(size_t)MF * Fq / 4 / 256, 256>>>(xb, hh, hl);
        else
            gemm_p<128,1><<<g1, 256, DYN128>>>(zh, zl, W1Th, W1Tl, nullptr, xb, nullptr,
                                               hh, hl, nullptr, nullptr, Dq, Fq, 0,0,0,0);
        // f = h @ W2 + b2
        if (i < 5) {
            // fused: f, g-history, z-history, z_new, z planes
            gemm_p<64,2><<<g2, 256, DYN64>>>(hh, hl, W2Th, W2Tl, b2, nullptr, z,
                                             zh, zl, Gh0 + (size_t)(i & 3) * TOT,
                                             Zh0 + (size_t)(i & 3) * TOT, Fq, Dq, 0,0,0,0);
        } else {
            const int s1 = (i - 1) & 3, s2 = (i - 2) & 3, s3 = (i - 3) & 3, s4 = (i - 4) & 3;
            cudaMemsetAsync(red, 0, 28 * sizeof(float));
            // fused: f = h@W2 + b2 AND reduce partials (reads z via Dm)
            gemm_p<64,3><<<g2, 256, DYN64>>>(hh, hl, W2Th, W2Tl, b2, z, f,
                                             nullptr, nullptr, nullptr, nullptr,
                                             Fq, Dq, s1, s2, s3, s4);
            float* dst = (i == 11) ? out : z;
            upd_anderson<<<upd_blocks, 256>>>(f, z, dst, s1, s2, s3, s4, i & 3);
        }
    }
}

// round 13
// speedup vs baseline: 1.4620x; 1.3169x over previous
#include <cuda_runtime.h>
#include <cuda_fp16.h>
#include <math.h>
#include <stdint.h>

// Problem constants
#define Bq   2
#define Sq   1024
#define Dq   512
#define Fq   2048
#define MF   (Bq*Sq)          // 2048 GEMM rows
#define FLAT (Sq*Dq)          // 524288 per-batch flat size (2^19)
#define TOT  (Bq*FLAT)        // 1048576
#define LAMv 1e-4f

// ---------------- scratch (no allocations allowed) ----------------
__device__ float g_xb[(size_t)MF*Fq];   // x@Wx + b1 (16MB)
__device__ float g_z [TOT];             // current z (fp32)
__device__ float g_f [TOT];             // f(z) (only used i>=5)
__device__ float g_Gh[4][TOT];          // g history, circular
__device__ float g_Zh[4][TOT];          // z history, circular
__device__ float g_red[2*14];
__device__ float g_gamma[2*4];

// fp16 planes: weights single, activations hi/lo (error-compensated split)
__device__ __half g_W1T[(size_t)Fq*Dq];  // [N=2048][K=512]
__device__ __half g_WxT[(size_t)Fq*Dq];
__device__ __half g_W2T[(size_t)Dq*Fq];  // [512][2048]
__device__ __half g_xp [2][TOT];
__device__ __half g_zp [2][TOT];
__device__ __half g_hp [2][(size_t)MF*Fq];

// ======================= helpers =======================
__device__ __forceinline__ uint32_t smem_u32(const void* p){
    uint32_t a;
    asm("{ .reg .u64 t; cvta.to.shared.u64 t, %1; cvt.u32.u64 %0, t; }" : "=r"(a) : "l"(p));
    return a;
}
#define SWZ(o) ((o) ^ (((o) >> 3) & 0x70))

__device__ __forceinline__ void ldm4(uint32_t* r, uint32_t addr){
    asm volatile("ldmatrix.sync.aligned.m8n8.x4.shared.b16 {%0,%1,%2,%3}, [%4];"
        : "=r"(r[0]), "=r"(r[1]), "=r"(r[2]), "=r"(r[3]) : "r"(addr));
}
__device__ __forceinline__ void mma_f16(float* c, const uint32_t* a, const uint32_t* b){
    asm volatile("mma.sync.aligned.m16n8k16.row.col.f32.f16.f16.f32 "
        "{%0,%1,%2,%3}, {%4,%5,%6,%7}, {%8,%9}, {%0,%1,%2,%3};"
        : "+f"(c[0]), "+f"(c[1]), "+f"(c[2]), "+f"(c[3])
        : "r"(a[0]), "r"(a[1]), "r"(a[2]), "r"(a[3]), "r"(b[0]), "r"(b[1]));
}
__device__ __forceinline__ void cpasync16(uint32_t dst, const void* src){
    asm volatile("cp.async.cg.shared.global [%0], [%1], 16;" :: "r"(dst), "l"(src));
}
__device__ __forceinline__ void cpcommit(){ asm volatile("cp.async.commit_group;" ::: "memory"); }
template<int N> __device__ __forceinline__ void cpwait(){
    asm volatile("cp.async.wait_group %0;" :: "n"(N) : "memory");
}
__device__ __forceinline__ __half2 split_hi(float a, float b){
    return __floats2half2_rn(a, b);
}
__device__ __forceinline__ __half2 split_lo(float a, float b, __half2 h){
    return __floats2half2_rn(a - __half2float(__low2half(h)),
                             b - __half2float(__high2half(h)));
}

// ---------------- 4x4 Schur-complement solve (device, replicates reference) ----------------
__device__ __forceinline__ void inv2x2d(const float m[4], float o[4])
{
    float invDet = 1.f / (m[0] * m[3] - m[1] * m[2] + 1e-6f);
    o[0] =  m[3] * invDet; o[1] = -m[1] * invDet;
    o[2] = -m[2] * invDet; o[3] =  m[0] * invDet;
}
__device__ __forceinline__ void mul2x2d(const float a[4], const float b[4], float o[4])
{
    o[0] = a[0] * b[0] + a[1] * b[2]; o[1] = a[0] * b[1] + a[1] * b[3];
    o[2] = a[2] * b[0] + a[3] * b[2]; o[3] = a[2] * b[1] + a[3] * b[3];
}
__device__ void solve_gamma(const float* r, float* gam)
{
    float H[4][4];
    H[0][0] = r[0] + LAMv; H[0][1] = r[1];        H[0][2] = r[2];        H[0][3] = r[3];
    H[1][0] = r[1];        H[1][1] = r[4] + LAMv; H[1][2] = r[5];        H[1][3] = r[6];
    H[2][0] = r[2];        H[2][1] = r[5];        H[2][2] = r[7] + LAMv; H[2][3] = r[8];
    H[3][0] = r[3];        H[3][1] = r[6];        H[3][2] = r[8];        H[3][3] = r[9] + LAMv;
    float y[4] = { r[10], r[11], r[12], r[13] };

    float A_[4] = { H[0][0], H[0][1], H[1][0], H[1][1] };
    float Bb[4] = { H[0][2], H[0][3], H[1][2], H[1][3] };
    float C_[4] = { H[2][0], H[2][1], H[3][0], H[3][1] };
    float Dd[4] = { H[2][2], H[2][3], H[3][2], H[3][3] };

    float Ai[4];   inv2x2d(A_, Ai);
    float CAi[4];  mul2x2d(C_, Ai, CAi);
    float CAiB[4]; mul2x2d(CAi, Bb, CAiB);
    float Sch[4]  = { Dd[0] - CAiB[0], Dd[1] - CAiB[1], Dd[2] - CAiB[2], Dd[3] - CAiB[3] };
    float Si[4];   inv2x2d(Sch, Si);
    float SiCAi[4]; mul2x2d(Si, CAi, SiCAi);
    float AiB[4];   mul2x2d(Ai, Bb, AiB);
    float t11[4];   mul2x2d(AiB, SiCAi, t11);
    float b11[4] = { Ai[0] + t11[0], Ai[1] + t11[1], Ai[2] + t11[2], Ai[3] + t11[3] };
    float b12[4];   mul2x2d(AiB, Si, b12);
    b12[0] = -b12[0]; b12[1] = -b12[1]; b12[2] = -b12[2]; b12[3] = -b12[3];

    float inv[4][4] = {
        { b11[0],  b11[1],  b12[0],  b12[1] },
        { b11[2],  b11[3],  b12[2],  b12[3] },
        { -SiCAi[0], -SiCAi[1], Si[0], Si[1] },
        { -SiCAi[2], -SiCAi[3], Si[2], Si[3] }
    };
#pragma unroll
    for (int j = 0; j < 4; j++)
        gam[j] = inv[j][0] * y[0] + inv[j][1] * y[1]
               + inv[j][2] * y[2] + inv[j][3] * y[3];
}

// ======================= pipelined split-fp16 mma.sync GEMM =======================
// CTA tile 128(M) x BN, K-slab 64, SW128, 3-stage cp.async.
// A planes: [M x K] fp16 hi/lo (a = ah + al).  B plane: [N x K] fp16 (weights).
// acc = ah@b + al@b  (2 MMAs/tile; error = weight rounding ~2^-11, random-sign)
// MODE 0: C fp32 = acc + bias[n]
// MODE 1: t = tanh(acc + Dm[m][n]); write Chp/Clp fp16 hi/lo planes
// MODE 2: f = acc + bias[n]; fused upd_simple (C holds z in/out)
// MODE 3: f = acc + bias[n]; C=f; fused reduce_k partials (Dm holds z input)
template<int BN, int MODE>
__global__ __launch_bounds__(256, 1) void gemm_p(
    const __half* __restrict__ Ahp, const __half* __restrict__ Alp,
    const __half* __restrict__ Bp,
    const float* __restrict__ bias, const float* __restrict__ Dm,
    float* __restrict__ C,
    __half* __restrict__ Chp, __half* __restrict__ Clp,
    float* __restrict__ Ghs, float* __restrict__ Zhs,
    int K, int ldn, int s1, int s2, int s3, int s4)
{
    constexpr int ASTG = 128 * 64 * 2;         // one A plane per stage (16 KB)
    constexpr int BSTG = BN  * 64 * 2;         // B plane per stage
    constexpr int STG  = 2 * ASTG + BSTG;      // stage size
    constexpr int BIT  = (BN * 8) / 256;       // B chunks per thread
    constexpr int NT   = BN / 16;              // n8-tiles per warp

    extern __shared__ char dynraw[];
    char* dyn = (char*)(((uintptr_t)dynraw + 1023) & ~(uintptr_t)1023);

    const int tid  = threadIdx.x;
    const int wid  = tid >> 5;
    const int lane = tid & 31;
    const int m0w  = (wid & 3) * 32;
    const int n0w  = (wid >> 2) * (BN / 2);
    const int NS   = K >> 6;

    float acc[2][NT][4];
#pragma unroll
    for (int mt = 0; mt < 2; mt++)
#pragma unroll
        for (int nt = 0; nt < NT; nt++)
#pragma unroll
            for (int v = 0; v < 4; v++) acc[mt][nt][v] = 0.f;

    auto issue = [&](int s, int st){
        char* buf = dyn + st * STG;
        uint32_t ba = smem_u32(buf);
        const __half* ap[2] = { Ahp, Alp };
#pragma unroll
        for (int p = 0; p < 2; p++)
#pragma unroll
            for (int it = 0; it < 4; it++) {
                int c = tid + it * 256;          // 0..1023
                int row = c >> 3, kc = c & 7;
                const void* src = ap[p] + (size_t)(blockIdx.y * 128 + row) * K + s * 64 + kc * 8;
                cpasync16(ba + p * ASTG + SWZ((uint32_t)(row * 128 + kc * 16)), src);
            }
#pragma unroll
        for (int it = 0; it < BIT; it++) {
            int c = tid + it * 256;
            int row = c >> 3, kc = c & 7;
            const void* src = Bp + (size_t)(blockIdx.x * BN + row) * K + s * 64 + kc * 8;
            cpasync16(ba + 2 * ASTG + SWZ((uint32_t)(row * 128 + kc * 16)), src);
        }
    };

    issue(0, 0); cpcommit();
    issue(1, 1); cpcommit();

    const int arow = lane & 15;
    const int brow = (lane & 7) | ((lane >> 1) & 8);
    const int asel = lane >> 4;
    const int bsel = (lane >> 3) & 1;

    for (int s = 0; s < NS; s++) {
        const int st = s % 3;
        if (s + 2 < NS) issue(s + 2, (s + 2) % 3);
        cpcommit();
        cpwait<2>();
        __syncthreads();

        const uint32_t bAh = smem_u32(dyn + st * STG);
        const uint32_t bAl = bAh + ASTG;
        const uint32_t bB  = bAh + 2 * ASTG;

#pragma unroll
        for (int ks = 0; ks < 4; ks++) {
            uint32_t ah[2][4], al[2][4];
            const int achunk = (ks << 1) + asel;
#pragma unroll
            for (int mt = 0; mt < 2; mt++) {
                uint32_t off = SWZ((uint32_t)((m0w + mt * 16 + arow) * 128 + achunk * 16));
                ldm4(ah[mt], bAh + off);
                ldm4(al[mt], bAl + off);
            }
            uint32_t bh[NT][2];
            const int bchunk = (ks << 1) + bsel;
#pragma unroll
            for (int np = 0; np < NT / 2; np++) {
                uint32_t off = SWZ((uint32_t)((n0w + np * 16 + brow) * 128 + bchunk * 16));
                uint32_t r[4];
                ldm4(r, bB + off);
                bh[2*np][0] = r[0]; bh[2*np][1] = r[1];
                bh[2*np+1][0] = r[2]; bh[2*np+1][1] = r[3];
            }
#pragma unroll
            for (int mt = 0; mt < 2; mt++)
#pragma unroll
                for (int nt = 0; nt < NT; nt++)
                    mma_f16(acc[mt][nt], ah[mt], bh[nt]);
#pragma unroll
            for (int mt = 0; mt < 2; mt++)
#pragma unroll
                for (int nt = 0; nt < NT; nt++)
                    mma_f16(acc[mt][nt], al[mt], bh[nt]);
        }
        __syncthreads();
    }

    // ---------- epilogue ----------
    float part[14];
    if (MODE == 3) {
#pragma unroll
        for (int v = 0; v < 14; v++) part[v] = 0.f;
    }
#pragma unroll
    for (int mt = 0; mt < 2; mt++) {
        const int gm = blockIdx.y * 128 + m0w + mt * 16 + (lane >> 2);
#pragma unroll
        for (int nt = 0; nt < NT; nt++) {
            const int gn = blockIdx.x * BN + n0w + nt * 8 + ((lane & 3) << 1);
            const size_t o0 = (size_t)gm * ldn + gn;
            const size_t o1 = (size_t)(gm + 8) * ldn + gn;
            if (MODE == 0) {
                float2 bv = *(const float2*)(bias + gn);
                float2 r0, r1;
                r0.x = acc[mt][nt][0] + bv.x;  r0.y = acc[mt][nt][1] + bv.y;
                r1.x = acc[mt][nt][2] + bv.x;  r1.y = acc[mt][nt][3] + bv.y;
                *(float2*)(C + o0) = r0;
                *(float2*)(C + o1) = r1;
            } else if (MODE == 1) {
                float2 d0 = *(const float2*)(Dm + o0);
                float2 d1 = *(const float2*)(Dm + o1);
                float t0 = tanhf(acc[mt][nt][0] + d0.x);
                float t1 = tanhf(acc[mt][nt][1] + d0.y);
                float t2 = tanhf(acc[mt][nt][2] + d1.x);
                float t3 = tanhf(acc[mt][nt][3] + d1.y);
                __half2 h0 = split_hi(t0, t1);
                __half2 h1 = split_hi(t2, t3);
                *(__half2*)(Chp + o0) = h0;
                *(__half2*)(Chp + o1) = h1;
                *(__half2*)(Clp + o0) = split_lo(t0, t1, h0);
                *(__half2*)(Clp + o1) = split_lo(t2, t3, h1);
            } else if (MODE == 2) {
                float2 bv = *(const float2*)(bias + gn);
                float f0 = acc[mt][nt][0] + bv.x;
                float f1 = acc[mt][nt][1] + bv.y;
                float f2 = acc[mt][nt][2] + bv.x;
                float f3 = acc[mt][nt][3] + bv.y;
                float2 z0 = *(const float2*)(C + o0);
                float2 z1 = *(const float2*)(C + o1);
                float2 gg0 = { f0 - z0.x, f1 - z0.y };
                float2 gg1 = { f2 - z1.x, f3 - z1.y };
                *(float2*)(Ghs + o0) = gg0;
                *(float2*)(Ghs + o1) = gg1;
                *(float2*)(Zhs + o0) = z0;
                *(float2*)(Zhs + o1) = z1;
                float2 w0 = { f0, f1 }, w1 = { f2, f3 };
                *(float2*)(C + o0) = w0;
                *(float2*)(C + o1) = w1;
                __half2 h0 = split_hi(f0, f1);
                __half2 h1 = split_hi(f2, f3);
                *(__half2*)(Chp + o0) = h0;
                *(__half2*)(Chp + o1) = h1;
                *(__half2*)(Clp + o0) = split_lo(f0, f1, h0);
                *(__half2*)(Clp + o1) = split_lo(f2, f3, h1);
            } else {
                // MODE 3: f = acc + bias; write f; accumulate reduce partials
                float2 bv = *(const float2*)(bias + gn);
                float fr[4];
                fr[0] = acc[mt][nt][0] + bv.x;
                fr[1] = acc[mt][nt][1] + bv.y;
                fr[2] = acc[mt][nt][2] + bv.x;
                fr[3] = acc[mt][nt][3] + bv.y;
                *(float2*)(C + o0) = *(float2*)&fr[0];
                *(float2*)(C + o1) = *(float2*)&fr[2];
                float2 z0 = *(const float2*)(Dm + o0);
                float2 z1 = *(const float2*)(Dm + o1);
                float gg[4] = { fr[0] - z0.x, fr[1] - z0.y, fr[2] - z1.x, fr[3] - z1.y };
                float2 h1a = *(const float2*)(&g_Gh[s1][0] + o0);
                float2 h1b = *(const float2*)(&g_Gh[s1][0] + o1);
                float2 h2a = *(const float2*)(&g_Gh[s2][0] + o0);
                float2 h2b = *(const float2*)(&g_Gh[s2][0] + o1);
                float2 h3a = *(const float2*)(&g_Gh[s3][0] + o0);
                float2 h3b = *(const float2*)(&g_Gh[s3][0] + o1);
                float2 h4a = *(const float2*)(&g_Gh[s4][0] + o0);
                float2 h4b = *(const float2*)(&g_Gh[s4][0] + o1);
                float hv[4][4] = {
                    { h1a.x, h1a.y, h1b.x, h1b.y },
                    { h2a.x, h2a.y, h2b.x, h2b.y },
                    { h3a.x, h3a.y, h3b.x, h3b.y },
                    { h4a.x, h4a.y, h4b.x, h4b.y }
                };
#pragma unroll
                for (int e = 0; e < 4; e++) {
                    float g  = gg[e];
                    float d0 = g - hv[0][e];
                    float d1 = g - hv[1][e];
                    float d2 = g - hv[2][e];
                    float d3 = g - hv[3][e];
                    part[0] += d0 * d0; part[1] += d0 * d1; part[2] += d0 * d2; part[3] += d0 * d3;
                    part[4] += d1 * d1; part[5] += d1 * d2; part[6] += d1 * d3;
                    part[7] += d2 * d2; part[8] += d2 * d3; part[9] += d3 * d3;
                    part[10] += d0 * g; part[11] += d1 * g; part[12] += d2 * g; part[13] += d3 * g;
                }
            }
        }
    }

    if (MODE == 3) {
        __shared__ float sred[8][14];
#pragma unroll
        for (int v = 0; v < 14; v++)
#pragma unroll
            for (int o = 16; o > 0; o >>= 1)
                part[v] += __shfl_down_sync(0xffffffffu, part[v], o);
        if (lane == 0) {
#pragma unroll
            for (int v = 0; v < 14; v++) sred[wid][v] = part[v];
        }
        __syncthreads();
        if (tid < 14) {
            float ssum = 0.f;
#pragma unroll
            for (int w = 0; w < 8; w++) ssum += sred[w][tid];
            int batch = blockIdx.y >> 3;   // 128 rows/block, 1024 rows/batch
            atomicAdd(&g_red[batch * 14 + tid], ssum);
        }
    }
}

// ---------------- one-time converters ----------------
__global__ void conv_wT(const float* __restrict__ W,
                        __half* __restrict__ T, int K, int N)
{
    __shared__ float t[32][33];
    int n0 = blockIdx.x * 32, k0 = blockIdx.y * 32;
    int tx = threadIdx.x, ty = threadIdx.y;   // 32 x 8
#pragma unroll
    for (int r = 0; r < 32; r += 8)
        t[ty + r][tx] = W[(size_t)(k0 + ty + r) * N + n0 + tx];
    __syncthreads();
#pragma unroll
    for (int r = 0; r < 32; r += 8) {
        float v = t[tx][ty + r];
        T[(size_t)(n0 + ty + r) * K + k0 + tx] = __float2half_rn(v);
    }
}
__global__ void conv_plane(const float* __restrict__ X,
                           __half* __restrict__ Xh, __half* __restrict__ Xl)
{
    int i = blockIdx.x * blockDim.x + threadIdx.x;
    float4 v = ((const float4*)X)[i];
    __half2 h01 = split_hi(v.x, v.y), h23 = split_hi(v.z, v.w);
    ((__half2*)Xh)[i*2]   = h01;
    ((__half2*)Xh)[i*2+1] = h23;
    ((__half2*)Xl)[i*2]   = split_lo(v.x, v.y, h01);
    ((__half2*)Xl)[i*2+1] = split_lo(v.z, v.w, h23);
}

// ---------------- iteration 0: h = tanh(xb) ----------------
__global__ void tanh_map(const float* __restrict__ src,
                         __half* __restrict__ Hh, __half* __restrict__ Hl)
{
    int i = blockIdx.x * blockDim.x + threadIdx.x;
    float4 v = ((const float4*)src)[i];
    v.x = tanhf(v.x); v.y = tanhf(v.y); v.z = tanhf(v.z); v.w = tanhf(v.w);
    __half2 h01 = split_hi(v.x, v.y), h23 = split_hi(v.z, v.w);
    ((__half2*)Hh)[i*2]   = h01;
    ((__half2*)Hh)[i*2+1] = h23;
    ((__half2*)Hl)[i*2]   = split_lo(v.x, v.y, h01);
    ((__half2*)Hl)[i*2+1] = split_lo(v.z, v.w, h23);
}

// ---------------- Anderson mixed update (fused gamma solve, + z planes) ----------------
__global__ void upd_anderson(const float* __restrict__ f, float* __restrict__ z,
                             float* __restrict__ dst,
                             int s1, int s2, int s3, int s4, int sw)
{
    __shared__ float sg[8];
    if (threadIdx.x < 2)
        solve_gamma(&g_red[threadIdx.x * 14], &sg[threadIdx.x * 4]);
    __syncthreads();

    int i = blockIdx.x * blockDim.x + threadIdx.x;
    int b = i >> 17;
    float ga0 = sg[b * 4 + 0];
    float ga1 = sg[b * 4 + 1];
    float ga2 = sg[b * 4 + 2];
    float ga3 = sg[b * 4 + 3];

    float4 fv = ((const float4*)f)[i];
    float4 zv = ((const float4*)z)[i];
    float4 G1 = ((const float4*)g_Gh[s1])[i];
    float4 G2 = ((const float4*)g_Gh[s2])[i];
    float4 G3 = ((const float4*)g_Gh[s3])[i];
    float4 G4 = ((const float4*)g_Gh[s4])[i];
    float4 Z1 = ((const float4*)g_Zh[s1])[i];
    float4 Z2 = ((const float4*)g_Zh[s2])[i];
    float4 Z3 = ((const float4*)g_Zh[s3])[i];
    float4 Z4 = ((const float4*)g_Zh[s4])[i];

    float4 gv, ov;
    float* fa = (float*)&fv;  float* za = (float*)&zv;
    float* g1 = (float*)&G1;  float* g2 = (float*)&G2;
    float* g3 = (float*)&G3;  float* g4 = (float*)&G4;
    float* z1 = (float*)&Z1;  float* z2 = (float*)&Z2;
    float* z3 = (float*)&Z3;  float* z4 = (float*)&Z4;
    float* gva = (float*)&gv; float* ova = (float*)&ov;

#pragma unroll
    for (int c = 0; c < 4; c++) {
        float zc = za[c];
        float g  = fa[c] - zc;
        float corr = ga0 * ((zc - z1[c]) + (g - g1[c]))
                   + ga1 * ((zc - z2[c]) + (g - g2[c]))
                   + ga2 * ((zc - z3[c]) + (g - g3[c]))
                   + ga3 * ((zc - z4[c]) + (g - g4[c]));
        gva[c] = g;
        ova[c] = zc + g - corr;
    }
    ((float4*)g_Gh[sw])[i] = gv;
    ((float4*)g_Zh[sw])[i] = zv;
    ((float4*)dst)[i] = ov;
    __half2 h01 = split_hi(ov.x, ov.y), h23 = split_hi(ov.z, ov.w);
    ((__half2*)g_zp[0])[i*2]   = h01;
    ((__half2*)g_zp[0])[i*2+1] = h23;
    ((__half2*)g_zp[1])[i*2]   = split_lo(ov.x, ov.y, h01);
    ((__half2*)g_zp[1])[i*2+1] = split_lo(ov.z, ov.w, h23);
}

// ---------------- launcher ----------------
extern "C" void kernel_launch(void* const* d_in, const int* in_sizes, int n_in,
                              void* d_out, int out_size)
{
    (void)in_sizes; (void)n_in; (void)out_size;
    const float* x  = (const float*)d_in[0];
    const float* W1 = (const float*)d_in[1];
    const float* Wx = (const float*)d_in[2];
    const float* b1 = (const float*)d_in[3];
    const float* W2 = (const float*)d_in[4];
    const float* b2 = (const float*)d_in[5];
    float* out = (float*)d_out;

    float *xb, *z, *f, *red, *Gh0, *Zh0;
    cudaGetSymbolAddress((void**)&xb,  g_xb);
    cudaGetSymbolAddress((void**)&z,   g_z);
    cudaGetSymbolAddress((void**)&f,   g_f);
    cudaGetSymbolAddress((void**)&red, g_red);
    cudaGetSymbolAddress((void**)&Gh0, g_Gh);
    cudaGetSymbolAddress((void**)&Zh0, g_Zh);
    __half *W1T, *WxT, *W2T, *xh, *xl, *zh, *zl, *hh, *hl;
    cudaGetSymbolAddress((void**)&W1T, g_W1T);
    cudaGetSymbolAddress((void**)&WxT, g_WxT);
    cudaGetSymbolAddress((void**)&W2T, g_W2T);
    cudaGetSymbolAddress((void**)&xh,  g_xp);  xl = xh + TOT;
    cudaGetSymbolAddress((void**)&zh,  g_zp);  zl = zh + TOT;
    cudaGetSymbolAddress((void**)&hh,  g_hp);  hl = hh + (size_t)MF*Fq;

    const int DYN128 = 3 * (2*128*64*2 + 128*64*2) + 1024;   // ~145 KB
    const int DYN64  = 3 * (2*128*64*2 +  64*64*2) + 1024;   // ~121 KB
    cudaFuncSetAttribute(gemm_p<128,0>, cudaFuncAttributeMaxDynamicSharedMemorySize, DYN128);
    cudaFuncSetAttribute(gemm_p<128,1>, cudaFuncAttributeMaxDynamicSharedMemorySize, DYN128);
    cudaFuncSetAttribute(gemm_p<64,0>,  cudaFuncAttributeMaxDynamicSharedMemorySize, DYN64);
    cudaFuncSetAttribute(gemm_p<64,2>,  cudaFuncAttributeMaxDynamicSharedMemorySize, DYN64);
    cudaFuncSetAttribute(gemm_p<64,3>,  cudaFuncAttributeMaxDynamicSharedMemorySize, DYN64);

    cudaMemsetAsync(z, 0, (size_t)TOT * sizeof(float));

    // one-time conversions
    dim3 tb(32, 8);
    conv_wT<<<dim3(Fq/32, Dq/32), tb>>>(W1, W1T, Dq, Fq);
    conv_wT<<<dim3(Fq/32, Dq/32), tb>>>(Wx, WxT, Dq, Fq);
    conv_wT<<<dim3(Dq/32, Fq/32), tb>>>(W2, W2T, Fq, Dq);
    conv_plane<<<TOT/4/256, 256>>>(x, xh, xl);

    dim3 g1(Fq / 128, MF / 128);   // 16 x 16
    dim3 g2(Dq / 64,  MF / 128);   // 8 x 16

    // xb = x @ Wx + b1
    gemm_p<128,0><<<g1, 256, DYN128>>>(xh, xl, WxT, b1, nullptr, xb,
                                       nullptr, nullptr, nullptr, nullptr, Dq, Fq, 0,0,0,0);

    const int upd_blocks = TOT / 4 / 256;
    for (int i = 0; i < 12; i++) {
        // h = tanh(z @ W1 + xb)  -> fp16 hi/lo planes
        if (i == 0)
            tanh_map<<<(size_t)MF * Fq / 4 / 256, 256>>>(xb, hh, hl);
        else
            gemm_p<128,1><<<g1, 256, DYN128>>>(zh, zl, W1T, nullptr, xb, nullptr,
                                               hh, hl, nullptr, nullptr, Dq, Fq, 0,0,0,0);
        // f = h @ W2 + b2
        if (i < 5) {
            // fused: f, g-history, z-history, z_new, z planes
            gemm_p<64,2><<<g2, 256, DYN64>>>(hh, hl, W2T, b2, nullptr, z,
                                             zh, zl, Gh0 + (size_t)(i & 3) * TOT,
                                             Zh0 + (size_t)(i & 3) * TOT, Fq, Dq, 0,0,0,0);
        } else {
            const int s1 = (i - 1) & 3, s2 = (i - 2) & 3, s3 = (i - 3) & 3, s4 = (i - 4) & 3;
            cudaMemsetAsync(red, 0, 28 * sizeof(float));
            // fused: f = h@W2 + b2 AND reduce partials (reads z via Dm)
            gemm_p<64,3><<<g2, 256, DYN64>>>(hh, hl, W2T, b2, z, f,
                                             nullptr, nullptr, nullptr, nullptr,
                                             Fq, Dq, s1, s2, s3, s4);
            float* dst = (i == 11) ? out : z;
            upd_anderson<<<upd_blocks, 256>>>(f, z, dst, s1, s2, s3, s4, i & 3);
        }
    }
}

// round 14
// speedup vs baseline: 1.7297x; 1.1831x over previous
#include <cuda_runtime.h>
#include <cuda_fp16.h>
#include <math.h>
#include <stdint.h>

// Problem constants
#define Bq   2
#define Sq   1024
#define Dq   512
#define Fq   2048
#define MF   (Bq*Sq)          // 2048 GEMM rows
#define FLAT (Sq*Dq)          // 524288 per-batch flat size (2^19)
#define TOT  (Bq*FLAT)        // 1048576
#define LAMv 1e-4f

// ---------------- scratch (no allocations allowed) ----------------
__device__ float g_xb[(size_t)MF*Fq];   // x@Wx + b1 (16MB)
__device__ float g_z [TOT];             // current z (fp32)
__device__ float g_f [TOT];             // f(z) (only used i>=5)
__device__ float g_Gh[4][TOT];          // g history, circular
__device__ float g_Zh[4][TOT];          // z history, circular
__device__ float g_red[2*14];
__device__ float g_gamma[2*4];

// fp16 planes: weights single; z split hi/lo; h single (tanh output, fp16-friendly)
__device__ __half g_W1T[(size_t)Fq*Dq];  // [N=2048][K=512]
__device__ __half g_WxT[(size_t)Fq*Dq];
__device__ __half g_W2T[(size_t)Dq*Fq];  // [512][2048]
__device__ __half g_xp [2][TOT];
__device__ __half g_zp [2][TOT];
__device__ __half g_hp [(size_t)MF*Fq];

// ======================= helpers =======================
__device__ __forceinline__ uint32_t smem_u32(const void* p){
    uint32_t a;
    asm("{ .reg .u64 t; cvta.to.shared.u64 t, %1; cvt.u32.u64 %0, t; }" : "=r"(a) : "l"(p));
    return a;
}
#define SWZ(o) ((o) ^ (((o) >> 3) & 0x70))

__device__ __forceinline__ void ldm4(uint32_t* r, uint32_t addr){
    asm volatile("ldmatrix.sync.aligned.m8n8.x4.shared.b16 {%0,%1,%2,%3}, [%4];"
        : "=r"(r[0]), "=r"(r[1]), "=r"(r[2]), "=r"(r[3]) : "r"(addr));
}
__device__ __forceinline__ void mma_f16(float* c, const uint32_t* a, const uint32_t* b){
    asm volatile("mma.sync.aligned.m16n8k16.row.col.f32.f16.f16.f32 "
        "{%0,%1,%2,%3}, {%4,%5,%6,%7}, {%8,%9}, {%0,%1,%2,%3};"
        : "+f"(c[0]), "+f"(c[1]), "+f"(c[2]), "+f"(c[3])
        : "r"(a[0]), "r"(a[1]), "r"(a[2]), "r"(a[3]), "r"(b[0]), "r"(b[1]));
}
__device__ __forceinline__ void cpasync16(uint32_t dst, const void* src){
    asm volatile("cp.async.cg.shared.global [%0], [%1], 16;" :: "r"(dst), "l"(src));
}
__device__ __forceinline__ void cpcommit(){ asm volatile("cp.async.commit_group;" ::: "memory"); }
template<int N> __device__ __forceinline__ void cpwait(){
    asm volatile("cp.async.wait_group %0;" :: "n"(N) : "memory");
}
__device__ __forceinline__ __half2 split_hi(float a, float b){
    return __floats2half2_rn(a, b);
}
__device__ __forceinline__ __half2 split_lo(float a, float b, __half2 h){
    return __floats2half2_rn(a - __half2float(__low2half(h)),
                             b - __half2float(__high2half(h)));
}

// ---------------- 4x4 Schur-complement solve (device, replicates reference) ----------------
__device__ __forceinline__ void inv2x2d(const float m[4], float o[4])
{
    float invDet = 1.f / (m[0] * m[3] - m[1] * m[2] + 1e-6f);
    o[0] =  m[3] * invDet; o[1] = -m[1] * invDet;
    o[2] = -m[2] * invDet; o[3] =  m[0] * invDet;
}
__device__ __forceinline__ void mul2x2d(const float a[4], const float b[4], float o[4])
{
    o[0] = a[0] * b[0] + a[1] * b[2]; o[1] = a[0] * b[1] + a[1] * b[3];
    o[2] = a[2] * b[0] + a[3] * b[2]; o[3] = a[2] * b[1] + a[3] * b[3];
}
__device__ void solve_gamma(const float* r, float* gam)
{
    float H[4][4];
    H[0][0] = r[0] + LAMv; H[0][1] = r[1];        H[0][2] = r[2];        H[0][3] = r[3];
    H[1][0] = r[1];        H[1][1] = r[4] + LAMv; H[1][2] = r[5];        H[1][3] = r[6];
    H[2][0] = r[2];        H[2][1] = r[5];        H[2][2] = r[7] + LAMv; H[2][3] = r[8];
    H[3][0] = r[3];        H[3][1] = r[6];        H[3][2] = r[8];        H[3][3] = r[9] + LAMv;
    float y[4] = { r[10], r[11], r[12], r[13] };

    float A_[4] = { H[0][0], H[0][1], H[1][0], H[1][1] };
    float Bb[4] = { H[0][2], H[0][3], H[1][2], H[1][3] };
    float C_[4] = { H[2][0], H[2][1], H[3][0], H[3][1] };
    float Dd[4] = { H[2][2], H[2][3], H[3][2], H[3][3] };

    float Ai[4];   inv2x2d(A_, Ai);
    float CAi[4];  mul2x2d(C_, Ai, CAi);
    float CAiB[4]; mul2x2d(CAi, Bb, CAiB);
    float Sch[4]  = { Dd[0] - CAiB[0], Dd[1] - CAiB[1], Dd[2] - CAiB[2], Dd[3] - CAiB[3] };
    float Si[4];   inv2x2d(Sch, Si);
    float SiCAi[4]; mul2x2d(Si, CAi, SiCAi);
    float AiB[4];   mul2x2d(Ai, Bb, AiB);
    float t11[4];   mul2x2d(AiB, SiCAi, t11);
    float b11[4] = { Ai[0] + t11[0], Ai[1] + t11[1], Ai[2] + t11[2], Ai[3] + t11[3] };
    float b12[4];   mul2x2d(AiB, Si, b12);
    b12[0] = -b12[0]; b12[1] = -b12[1]; b12[2] = -b12[2]; b12[3] = -b12[3];

    float inv[4][4] = {
        { b11[0],  b11[1],  b12[0],  b12[1] },
        { b11[2],  b11[3],  b12[2],  b12[3] },
        { -SiCAi[0], -SiCAi[1], Si[0], Si[1] },
        { -SiCAi[2], -SiCAi[3], Si[2], Si[3] }
    };
#pragma unroll
    for (int j = 0; j < 4; j++)
        gam[j] = inv[j][0] * y[0] + inv[j][1] * y[1]
               + inv[j][2] * y[2] + inv[j][3] * y[3];
}

// ======================= pipelined fp16 mma.sync GEMM =======================
// CTA tile 128(M) x BN, K-slab 64, SW128, 3-stage cp.async.
// ASPLIT=2: A = Ahp + Alp (error-compensated split, 2 MMAs/tile)
// ASPLIT=1: A = Ahp only (1 MMA/tile)
// B plane: [N x K] fp16 (weights, single).
// MODE 0: C fp32 = acc + bias[n]
// MODE 1: t = tanh(acc + Dm[m][n]); write Chp fp16 plane
// MODE 2: f = acc + bias[n]; fused upd_simple (C holds z in/out; z planes hi/lo)
// MODE 3: f = acc + bias[n]; C=f; fused reduce_k partials (Dm holds z input)
template<int BN, int MODE, int ASPLIT>
__global__ __launch_bounds__(256, 1) void gemm_p(
    const __half* __restrict__ Ahp, const __half* __restrict__ Alp,
    const __half* __restrict__ Bp,
    const float* __restrict__ bias, const float* __restrict__ Dm,
    float* __restrict__ C,
    __half* __restrict__ Chp, __half* __restrict__ Clp,
    float* __restrict__ Ghs, float* __restrict__ Zhs,
    int K, int ldn, int s1, int s2, int s3, int s4)
{
    constexpr int ASTG = 128 * 64 * 2;             // one A plane per stage (16 KB)
    constexpr int BSTG = BN  * 64 * 2;             // B plane per stage
    constexpr int STG  = ASPLIT * ASTG + BSTG;     // stage size
    constexpr int BIT  = (BN * 8) / 256;           // B chunks per thread
    constexpr int NT   = BN / 16;                  // n8-tiles per warp

    extern __shared__ char dynraw[];
    char* dyn = (char*)(((uintptr_t)dynraw + 1023) & ~(uintptr_t)1023);

    const int tid  = threadIdx.x;
    const int wid  = tid >> 5;
    const int lane = tid & 31;
    const int m0w  = (wid & 3) * 32;
    const int n0w  = (wid >> 2) * (BN / 2);
    const int NS   = K >> 6;

    float acc[2][NT][4];
#pragma unroll
    for (int mt = 0; mt < 2; mt++)
#pragma unroll
        for (int nt = 0; nt < NT; nt++)
#pragma unroll
            for (int v = 0; v < 4; v++) acc[mt][nt][v] = 0.f;

    auto issue = [&](int s, int st){
        char* buf = dyn + st * STG;
        uint32_t ba = smem_u32(buf);
        const __half* ap[2] = { Ahp, Alp };
#pragma unroll
        for (int p = 0; p < ASPLIT; p++)
#pragma unroll
            for (int it = 0; it < 4; it++) {
                int c = tid + it * 256;          // 0..1023
                int row = c >> 3, kc = c & 7;
                const void* src = ap[p] + (size_t)(blockIdx.y * 128 + row) * K + s * 64 + kc * 8;
                cpasync16(ba + p * ASTG + SWZ((uint32_t)(row * 128 + kc * 16)), src);
            }
#pragma unroll
        for (int it = 0; it < BIT; it++) {
            int c = tid + it * 256;
            int row = c >> 3, kc = c & 7;
            const void* src = Bp + (size_t)(blockIdx.x * BN + row) * K + s * 64 + kc * 8;
            cpasync16(ba + ASPLIT * ASTG + SWZ((uint32_t)(row * 128 + kc * 16)), src);
        }
    };

    issue(0, 0); cpcommit();
    issue(1, 1); cpcommit();

    const int arow = lane & 15;
    const int brow = (lane & 7) | ((lane >> 1) & 8);
    const int asel = lane >> 4;
    const int bsel = (lane >> 3) & 1;

    for (int s = 0; s < NS; s++) {
        const int st = s % 3;
        if (s + 2 < NS) issue(s + 2, (s + 2) % 3);
        cpcommit();
        cpwait<2>();
        __syncthreads();

        const uint32_t bAh = smem_u32(dyn + st * STG);
        const uint32_t bAl = bAh + ASTG;
        const uint32_t bB  = bAh + ASPLIT * ASTG;

#pragma unroll
        for (int ks = 0; ks < 4; ks++) {
            uint32_t ah[2][4], al[2][4];
            const int achunk = (ks << 1) + asel;
#pragma unroll
            for (int mt = 0; mt < 2; mt++) {
                uint32_t off = SWZ((uint32_t)((m0w + mt * 16 + arow) * 128 + achunk * 16));
                ldm4(ah[mt], bAh + off);
                if (ASPLIT == 2) ldm4(al[mt], bAl + off);
            }
            uint32_t bh[NT][2];
            const int bchunk = (ks << 1) + bsel;
#pragma unroll
            for (int np = 0; np < NT / 2; np++) {
                uint32_t off = SWZ((uint32_t)((n0w + np * 16 + brow) * 128 + bchunk * 16));
                uint32_t r[4];
                ldm4(r, bB + off);
                bh[2*np][0] = r[0]; bh[2*np][1] = r[1];
                bh[2*np+1][0] = r[2]; bh[2*np+1][1] = r[3];
            }
#pragma unroll
            for (int mt = 0; mt < 2; mt++)
#pragma unroll
                for (int nt = 0; nt < NT; nt++)
                    mma_f16(acc[mt][nt], ah[mt], bh[nt]);
            if (ASPLIT == 2) {
#pragma unroll
                for (int mt = 0; mt < 2; mt++)
#pragma unroll
                    for (int nt = 0; nt < NT; nt++)
                        mma_f16(acc[mt][nt], al[mt], bh[nt]);
            }
        }
        __syncthreads();
    }

    // ---------- epilogue ----------
    float part[14];
    if (MODE == 3) {
#pragma unroll
        for (int v = 0; v < 14; v++) part[v] = 0.f;
    }
#pragma unroll
    for (int mt = 0; mt < 2; mt++) {
        const int gm = blockIdx.y * 128 + m0w + mt * 16 + (lane >> 2);
#pragma unroll
        for (int nt = 0; nt < NT; nt++) {
            const int gn = blockIdx.x * BN + n0w + nt * 8 + ((lane & 3) << 1);
            const size_t o0 = (size_t)gm * ldn + gn;
            const size_t o1 = (size_t)(gm + 8) * ldn + gn;
            if (MODE == 0) {
                float2 bv = *(const float2*)(bias + gn);
                float2 r0, r1;
                r0.x = acc[mt][nt][0] + bv.x;  r0.y = acc[mt][nt][1] + bv.y;
                r1.x = acc[mt][nt][2] + bv.x;  r1.y = acc[mt][nt][3] + bv.y;
                *(float2*)(C + o0) = r0;
                *(float2*)(C + o1) = r1;
            } else if (MODE == 1) {
                float2 d0 = *(const float2*)(Dm + o0);
                float2 d1 = *(const float2*)(Dm + o1);
                float t0 = tanhf(acc[mt][nt][0] + d0.x);
                float t1 = tanhf(acc[mt][nt][1] + d0.y);
                float t2 = tanhf(acc[mt][nt][2] + d1.x);
                float t3 = tanhf(acc[mt][nt][3] + d1.y);
                *(__half2*)(Chp + o0) = split_hi(t0, t1);
                *(__half2*)(Chp + o1) = split_hi(t2, t3);
            } else if (MODE == 2) {
                float2 bv = *(const float2*)(bias + gn);
                float f0 = acc[mt][nt][0] + bv.x;
                float f1 = acc[mt][nt][1] + bv.y;
                float f2 = acc[mt][nt][2] + bv.x;
                float f3 = acc[mt][nt][3] + bv.y;
                float2 z0 = *(const float2*)(C + o0);
                float2 z1 = *(const float2*)(C + o1);
                float2 gg0 = { f0 - z0.x, f1 - z0.y };
                float2 gg1 = { f2 - z1.x, f3 - z1.y };
                *(float2*)(Ghs + o0) = gg0;
                *(float2*)(Ghs + o1) = gg1;
                *(float2*)(Zhs + o0) = z0;
                *(float2*)(Zhs + o1) = z1;
                float2 w0 = { f0, f1 }, w1 = { f2, f3 };
                *(float2*)(C + o0) = w0;
                *(float2*)(C + o1) = w1;
                __half2 h0 = split_hi(f0, f1);
                __half2 h1 = split_hi(f2, f3);
                *(__half2*)(Chp + o0) = h0;
                *(__half2*)(Chp + o1) = h1;
                *(__half2*)(Clp + o0) = split_lo(f0, f1, h0);
                *(__half2*)(Clp + o1) = split_lo(f2, f3, h1);
            } else {
                // MODE 3: f = acc + bias; write f; accumulate reduce partials
                float2 bv = *(const float2*)(bias + gn);
                float fr[4];
                fr[0] = acc[mt][nt][0] + bv.x;
                fr[1] = acc[mt][nt][1] + bv.y;
                fr[2] = acc[mt][nt][2] + bv.x;
                fr[3] = acc[mt][nt][3] + bv.y;
                *(float2*)(C + o0) = *(float2*)&fr[0];
                *(float2*)(C + o1) = *(float2*)&fr[2];
                float2 z0 = *(const float2*)(Dm + o0);
                float2 z1 = *(const float2*)(Dm + o1);
                float gg[4] = { fr[0] - z0.x, fr[1] - z0.y, fr[2] - z1.x, fr[3] - z1.y };
                float2 h1a = *(const float2*)(&g_Gh[s1][0] + o0);
                float2 h1b = *(const float2*)(&g_Gh[s1][0] + o1);
                float2 h2a = *(const float2*)(&g_Gh[s2][0] + o0);
                float2 h2b = *(const float2*)(&g_Gh[s2][0] + o1);
                float2 h3a = *(const float2*)(&g_Gh[s3][0] + o0);
                float2 h3b = *(const float2*)(&g_Gh[s3][0] + o1);
                float2 h4a = *(const float2*)(&g_Gh[s4][0] + o0);
                float2 h4b = *(const float2*)(&g_Gh[s4][0] + o1);
                float hv[4][4] = {
                    { h1a.x, h1a.y, h1b.x, h1b.y },
                    { h2a.x, h2a.y, h2b.x, h2b.y },
                    { h3a.x, h3a.y, h3b.x, h3b.y },
                    { h4a.x, h4a.y, h4b.x, h4b.y }
                };
#pragma unroll
                for (int e = 0; e < 4; e++) {
                    float g  = gg[e];
                    float d0 = g - hv[0][e];
                    float d1 = g - hv[1][e];
                    float d2 = g - hv[2][e];
                    float d3 = g - hv[3][e];
                    part[0] += d0 * d0; part[1] += d0 * d1; part[2] += d0 * d2; part[3] += d0 * d3;
                    part[4] += d1 * d1; part[5] += d1 * d2; part[6] += d1 * d3;
                    part[7] += d2 * d2; part[8] += d2 * d3; part[9] += d3 * d3;
                    part[10] += d0 * g; part[11] += d1 * g; part[12] += d2 * g; part[13] += d3 * g;
                }
            }
        }
    }

    if (MODE == 3) {
        __shared__ float sred[8][14];
#pragma unroll
        for (int v = 0; v < 14; v++)
#pragma unroll
            for (int o = 16; o > 0; o >>= 1)
                part[v] += __shfl_down_sync(0xffffffffu, part[v], o);
        if (lane == 0) {
#pragma unroll
            for (int v = 0; v < 14; v++) sred[wid][v] = part[v];
        }
        __syncthreads();
        if (tid < 14) {
            float ssum = 0.f;
#pragma unroll
            for (int w = 0; w < 8; w++) ssum += sred[w][tid];
            int batch = blockIdx.y >> 3;   // 128 rows/block, 1024 rows/batch
            atomicAdd(&g_red[batch * 14 + tid], ssum);
        }
    }
}

// ---------------- one-time converters ----------------
__global__ void conv_wT(const float* __restrict__ W,
                        __half* __restrict__ T, int K, int N)
{
    __shared__ float t[32][33];
    int n0 = blockIdx.x * 32, k0 = blockIdx.y * 32;
    int tx = threadIdx.x, ty = threadIdx.y;   // 32 x 8
#pragma unroll
    for (int r = 0; r < 32; r += 8)
        t[ty + r][tx] = W[(size_t)(k0 + ty + r) * N + n0 + tx];
    __syncthreads();
#pragma unroll
    for (int r = 0; r < 32; r += 8) {
        float v = t[tx][ty + r];
        T[(size_t)(n0 + ty + r) * K + k0 + tx] = __float2half_rn(v);
    }
}
__global__ void conv_plane(const float* __restrict__ X,
                           __half* __restrict__ Xh, __half* __restrict__ Xl)
{
    int i = blockIdx.x * blockDim.x + threadIdx.x;
    float4 v = ((const float4*)X)[i];
    __half2 h01 = split_hi(v.x, v.y), h23 = split_hi(v.z, v.w);
    ((__half2*)Xh)[i*2]   = h01;
    ((__half2*)Xh)[i*2+1] = h23;
    ((__half2*)Xl)[i*2]   = split_lo(v.x, v.y, h01);
    ((__half2*)Xl)[i*2+1] = split_lo(v.z, v.w, h23);
}

// ---------------- iteration 0: h = tanh(xb) ----------------
__global__ void tanh_map(const float* __restrict__ src, __half* __restrict__ Hh)
{
    int i = blockIdx.x * blockDim.x + threadIdx.x;
    float4 v = ((const float4*)src)[i];
    v.x = tanhf(v.x); v.y = tanhf(v.y); v.z = tanhf(v.z); v.w = tanhf(v.w);
    ((__half2*)Hh)[i*2]   = split_hi(v.x, v.y);
    ((__half2*)Hh)[i*2+1] = split_hi(v.z, v.w);
}

// ---------------- Anderson mixed update (fused gamma solve, + z planes) ----------------
__global__ void upd_anderson(const float* __restrict__ f, float* __restrict__ z,
                             float* __restrict__ dst,
                             int s1, int s2, int s3, int s4, int sw)
{
    __shared__ float sg[8];
    if (threadIdx.x < 2)
        solve_gamma(&g_red[threadIdx.x * 14], &sg[threadIdx.x * 4]);
    __syncthreads();

    int i = blockIdx.x * blockDim.x + threadIdx.x;
    int b = i >> 17;
    float ga0 = sg[b * 4 + 0];
    float ga1 = sg[b * 4 + 1];
    float ga2 = sg[b * 4 + 2];
    float ga3 = sg[b * 4 + 3];

    float4 fv = ((const float4*)f)[i];
    float4 zv = ((const float4*)z)[i];
    float4 G1 = ((const float4*)g_Gh[s1])[i];
    float4 G2 = ((const float4*)g_Gh[s2])[i];
    float4 G3 = ((const float4*)g_Gh[s3])[i];
    float4 G4 = ((const float4*)g_Gh[s4])[i];
    float4 Z1 = ((const float4*)g_Zh[s1])[i];
    float4 Z2 = ((const float4*)g_Zh[s2])[i];
    float4 Z3 = ((const float4*)g_Zh[s3])[i];
    float4 Z4 = ((const float4*)g_Zh[s4])[i];

    float4 gv, ov;
    float* fa = (float*)&fv;  float* za = (float*)&zv;
    float* g1 = (float*)&G1;  float* g2 = (float*)&G2;
    float* g3 = (float*)&G3;  float* g4 = (float*)&G4;
    float* z1 = (float*)&Z1;  float* z2 = (float*)&Z2;
    float* z3 = (float*)&Z3;  float* z4 = (float*)&Z4;
    float* gva = (float*)&gv; float* ova = (float*)&ov;

#pragma unroll
    for (int c = 0; c < 4; c++) {
        float zc = za[c];
        float g  = fa[c] - zc;
        float corr = ga0 * ((zc - z1[c]) + (g - g1[c]))
                   + ga1 * ((zc - z2[c]) + (g - g2[c]))
                   + ga2 * ((zc - z3[c]) + (g - g3[c]))
                   + ga3 * ((zc - z4[c]) + (g - g4[c]));
        gva[c] = g;
        ova[c] = zc + g - corr;
    }
    ((float4*)g_Gh[sw])[i] = gv;
    ((float4*)g_Zh[sw])[i] = zv;
    ((float4*)dst)[i] = ov;
    __half2 h01 = split_hi(ov.x, ov.y), h23 = split_hi(ov.z, ov.w);
    ((__half2*)g_zp[0])[i*2]   = h01;
    ((__half2*)g_zp[0])[i*2+1] = h23;
    ((__half2*)g_zp[1])[i*2]   = split_lo(ov.x, ov.y, h01);
    ((__half2*)g_zp[1])[i*2+1] = split_lo(ov.z, ov.w, h23);
}

// ---------------- launcher ----------------
extern "C" void kernel_launch(void* const* d_in, const int* in_sizes, int n_in,
                              void* d_out, int out_size)
{
    (void)in_sizes; (void)n_in; (void)out_size;
    const float* x  = (const float*)d_in[0];
    const float* W1 = (const float*)d_in[1];
    const float* Wx = (const float*)d_in[2];
    const float* b1 = (const float*)d_in[3];
    const float* W2 = (const float*)d_in[4];
    const float* b2 = (const float*)d_in[5];
    float* out = (float*)d_out;

    float *xb, *z, *f, *red, *Gh0, *Zh0;
    cudaGetSymbolAddress((void**)&xb,  g_xb);
    cudaGetSymbolAddress((void**)&z,   g_z);
    cudaGetSymbolAddress((void**)&f,   g_f);
    cudaGetSymbolAddress((void**)&red, g_red);
    cudaGetSymbolAddress((void**)&Gh0, g_Gh);
    cudaGetSymbolAddress((void**)&Zh0, g_Zh);
    __half *W1T, *WxT, *W2T, *xh, *xl, *zh, *zl, *hh;
    cudaGetSymbolAddress((void**)&W1T, g_W1T);
    cudaGetSymbolAddress((void**)&WxT, g_WxT);
    cudaGetSymbolAddress((void**)&W2T, g_W2T);
    cudaGetSymbolAddress((void**)&xh,  g_xp);  xl = xh + TOT;
    cudaGetSymbolAddress((void**)&zh,  g_zp);  zl = zh + TOT;
    cudaGetSymbolAddress((void**)&hh,  g_hp);

    const int DYN128 = 3 * (2*128*64*2 + 128*64*2) + 1024;   // ~145 KB (ASPLIT=2)
    const int DYN64S = 3 * (1*128*64*2 +  64*64*2) + 1024;   //  ~73 KB (ASPLIT=1)
    cudaFuncSetAttribute(gemm_p<128,0,2>, cudaFuncAttributeMaxDynamicSharedMemorySize, DYN128);
    cudaFuncSetAttribute(gemm_p<128,1,2>, cudaFuncAttributeMaxDynamicSharedMemorySize, DYN128);
    cudaFuncSetAttribute(gemm_p<64,2,1>,  cudaFuncAttributeMaxDynamicSharedMemorySize, DYN64S);
    cudaFuncSetAttribute(gemm_p<64,3,1>,  cudaFuncAttributeMaxDynamicSharedMemorySize, DYN64S);

    cudaMemsetAsync(z, 0, (size_t)TOT * sizeof(float));

    // one-time conversions
    dim3 tb(32, 8);
    conv_wT<<<dim3(Fq/32, Dq/32), tb>>>(W1, W1T, Dq, Fq);
    conv_wT<<<dim3(Fq/32, Dq/32), tb>>>(Wx, WxT, Dq, Fq);
    conv_wT<<<dim3(Dq/32, Fq/32), tb>>>(W2, W2T, Fq, Dq);
    conv_plane<<<TOT/4/256, 256>>>(x, xh, xl);

    dim3 g1(Fq / 128, MF / 128);   // 16 x 16
    dim3 g2(Dq / 64,  MF / 128);   // 8 x 16

    // xb = x @ Wx + b1   (x split 2-term: keep fp32-grade input path)
    gemm_p<128,0,2><<<g1, 256, DYN128>>>(xh, xl, WxT, b1, nullptr, xb,
                                         nullptr, nullptr, nullptr, nullptr, Dq, Fq, 0,0,0,0);

    const int upd_blocks = TOT / 4 / 256;
    for (int i = 0; i < 12; i++) {
        // h = tanh(z @ W1 + xb)  -> single fp16 plane
        if (i == 0)
            tanh_map<<<(size_t)MF * Fq / 4 / 256, 256>>>(xb, hh);
        else
            gemm_p<128,1,2><<<g1, 256, DYN128>>>(zh, zl, W1T, nullptr, xb, nullptr,
                                                 hh, nullptr, nullptr, nullptr, Dq, Fq, 0,0,0,0);
        // f = h @ W2 + b2   (h single-plane: 1 MMA/tile)
        if (i < 5) {
            // fused: f, g-history, z-history, z_new, z planes
            gemm_p<64,2,1><<<g2, 256, DYN64S>>>(hh, nullptr, W2T, b2, nullptr, z,
                                                zh, zl, Gh0 + (size_t)(i & 3) * TOT,
                                                Zh0 + (size_t)(i & 3) * TOT, Fq, Dq, 0,0,0,0);
        } else {
            const int s1 = (i - 1) & 3, s2 = (i - 2) & 3, s3 = (i - 3) & 3, s4 = (i - 4) & 3;
            cudaMemsetAsync(red, 0, 28 * sizeof(float));
            // fused: f = h@W2 + b2 AND reduce partials (reads z via Dm)
            gemm_p<64,3,1><<<g2, 256, DYN64S>>>(hh, nullptr, W2T, b2, z, f,
                                                nullptr, nullptr, nullptr, nullptr,
                                                Fq, Dq, s1, s2, s3, s4);
            float* dst = (i == 11) ? out : z;
            upd_anderson<<<upd_blocks, 256>>>(f, z, dst, s1, s2, s3, s4, i & 3);
        }
    }
}

// round 15
// speedup vs baseline: 1.9997x; 1.1561x over previous
#include <cuda_runtime.h>
#include <cuda_fp16.h>
#include <math.h>
#include <stdint.h>

// Problem constants
#define Bq   2
#define Sq   1024
#define Dq   512
#define Fq   2048
#define MF   (Bq*Sq)          // 2048 GEMM rows
#define FLAT (Sq*Dq)          // 524288 per-batch flat size (2^19)
#define TOT  (Bq*FLAT)        // 1048576
#define LAMv 1e-4f

// ---------------- scratch (no allocations allowed) ----------------
__device__ float g_xb[(size_t)MF*Fq];   // x@Wx + b1 (16MB)
__device__ float g_z [TOT];             // current z (fp32)
__device__ float g_f [TOT];             // f(z) (only used i>=5)
__device__ float g_Gh[4][TOT];          // g history, circular
__device__ float g_Zh[4][TOT];          // z history, circular
__device__ float g_red[2*14];
__device__ float g_gamma[2*4];

// fp16 planes: weights single; x split hi/lo (xb path); z and h single
__device__ __half g_W1T[(size_t)Fq*Dq];  // [N=2048][K=512]
__device__ __half g_WxT[(size_t)Fq*Dq];
__device__ __half g_W2T[(size_t)Dq*Fq];  // [512][2048]
__device__ __half g_xp [2][TOT];
__device__ __half g_zp [TOT];
__device__ __half g_hp [(size_t)MF*Fq];

// ======================= helpers =======================
__device__ __forceinline__ uint32_t smem_u32(const void* p){
    uint32_t a;
    asm("{ .reg .u64 t; cvta.to.shared.u64 t, %1; cvt.u32.u64 %0, t; }" : "=r"(a) : "l"(p));
    return a;
}
#define SWZ(o) ((o) ^ (((o) >> 3) & 0x70))

__device__ __forceinline__ void ldm4(uint32_t* r, uint32_t addr){
    asm volatile("ldmatrix.sync.aligned.m8n8.x4.shared.b16 {%0,%1,%2,%3}, [%4];"
        : "=r"(r[0]), "=r"(r[1]), "=r"(r[2]), "=r"(r[3]) : "r"(addr));
}
__device__ __forceinline__ void mma_f16(float* c, const uint32_t* a, const uint32_t* b){
    asm volatile("mma.sync.aligned.m16n8k16.row.col.f32.f16.f16.f32 "
        "{%0,%1,%2,%3}, {%4,%5,%6,%7}, {%8,%9}, {%0,%1,%2,%3};"
        : "+f"(c[0]), "+f"(c[1]), "+f"(c[2]), "+f"(c[3])
        : "r"(a[0]), "r"(a[1]), "r"(a[2]), "r"(a[3]), "r"(b[0]), "r"(b[1]));
}
__device__ __forceinline__ void cpasync16(uint32_t dst, const void* src){
    asm volatile("cp.async.cg.shared.global [%0], [%1], 16;" :: "r"(dst), "l"(src));
}
__device__ __forceinline__ void cpcommit(){ asm volatile("cp.async.commit_group;" ::: "memory"); }
template<int N> __device__ __forceinline__ void cpwait(){
    asm volatile("cp.async.wait_group %0;" :: "n"(N) : "memory");
}
__device__ __forceinline__ __half2 split_hi(float a, float b){
    return __floats2half2_rn(a, b);
}
__device__ __forceinline__ __half2 split_lo(float a, float b, __half2 h){
    return __floats2half2_rn(a - __half2float(__low2half(h)),
                             b - __half2float(__high2half(h)));
}

// ---------------- 4x4 Schur-complement solve (device, replicates reference) ----------------
__device__ __forceinline__ void inv2x2d(const float m[4], float o[4])
{
    float invDet = 1.f / (m[0] * m[3] - m[1] * m[2] + 1e-6f);
    o[0] =  m[3] * invDet; o[1] = -m[1] * invDet;
    o[2] = -m[2] * invDet; o[3] =  m[0] * invDet;
}
__device__ __forceinline__ void mul2x2d(const float a[4], const float b[4], float o[4])
{
    o[0] = a[0] * b[0] + a[1] * b[2]; o[1] = a[0] * b[1] + a[1] * b[3];
    o[2] = a[2] * b[0] + a[3] * b[2]; o[3] = a[2] * b[1] + a[3] * b[3];
}
__device__ void solve_gamma(const float* r, float* gam)
{
    float H[4][4];
    H[0][0] = r[0] + LAMv; H[0][1] = r[1];        H[0][2] = r[2];        H[0][3] = r[3];
    H[1][0] = r[1];        H[1][1] = r[4] + LAMv; H[1][2] = r[5];        H[1][3] = r[6];
    H[2][0] = r[2];        H[2][1] = r[5];        H[2][2] = r[7] + LAMv; H[2][3] = r[8];
    H[3][0] = r[3];        H[3][1] = r[6];        H[3][2] = r[8];        H[3][3] = r[9] + LAMv;
    float y[4] = { r[10], r[11], r[12], r[13] };

    float A_[4] = { H[0][0], H[0][1], H[1][0], H[1][1] };
    float Bb[4] = { H[0][2], H[0][3], H[1][2], H[1][3] };
    float C_[4] = { H[2][0], H[2][1], H[3][0], H[3][1] };
    float Dd[4] = { H[2][2], H[2][3], H[3][2], H[3][3] };

    float Ai[4];   inv2x2d(A_, Ai);
    float CAi[4];  mul2x2d(C_, Ai, CAi);
    float CAiB[4]; mul2x2d(CAi, Bb, CAiB);
    float Sch[4]  = { Dd[0] - CAiB[0], Dd[1] - CAiB[1], Dd[2] - CAiB[2], Dd[3] - CAiB[3] };
    float Si[4];   inv2x2d(Sch, Si);
    float SiCAi[4]; mul2x2d(Si, CAi, SiCAi);
    float AiB[4];   mul2x2d(Ai, Bb, AiB);
    float t11[4];   mul2x2d(AiB, SiCAi, t11);
    float b11[4] = { Ai[0] + t11[0], Ai[1] + t11[1], Ai[2] + t11[2], Ai[3] + t11[3] };
    float b12[4];   mul2x2d(AiB, Si, b12);
    b12[0] = -b12[0]; b12[1] = -b12[1]; b12[2] = -b12[2]; b12[3] = -b12[3];

    float inv[4][4] = {
        { b11[0],  b11[1],  b12[0],  b12[1] },
        { b11[2],  b11[3],  b12[2],  b12[3] },
        { -SiCAi[0], -SiCAi[1], Si[0], Si[1] },
        { -SiCAi[2], -SiCAi[3], Si[2], Si[3] }
    };
#pragma unroll
    for (int j = 0; j < 4; j++)
        gam[j] = inv[j][0] * y[0] + inv[j][1] * y[1]
               + inv[j][2] * y[2] + inv[j][3] * y[3];
}

// ======================= pipelined fp16 mma.sync GEMM =======================
// CTA tile 128(M) x BN, K-slab 64, SW128, 3-stage cp.async.
// ASPLIT=2: A = Ahp + Alp (error-compensated split).  ASPLIT=1: A = Ahp only.
// B plane: [N x K] fp16 (weights, single).
// MODE 0: C fp32 = acc + bias[n]
// MODE 1: t = tanh(acc + Dm[m][n]); write Chp fp16 plane
// MODE 2: f = acc + bias[n]; fused upd_simple (C holds z in/out; Chp = z plane)
// MODE 3: f = acc + bias[n]; C=f; fused reduce_k partials (Dm holds z input)
template<int BN, int MODE, int ASPLIT>
__global__ __launch_bounds__(256, 1) void gemm_p(
    const __half* __restrict__ Ahp, const __half* __restrict__ Alp,
    const __half* __restrict__ Bp,
    const float* __restrict__ bias, const float* __restrict__ Dm,
    float* __restrict__ C,
    __half* __restrict__ Chp,
    float* __restrict__ Ghs, float* __restrict__ Zhs,
    int K, int ldn, int s1, int s2, int s3, int s4)
{
    constexpr int ASTG = 128 * 64 * 2;             // one A plane per stage (16 KB)
    constexpr int BSTG = BN  * 64 * 2;             // B plane per stage
    constexpr int STG  = ASPLIT * ASTG + BSTG;     // stage size
    constexpr int BIT  = (BN * 8) / 256;           // B chunks per thread
    constexpr int NT   = BN / 16;                  // n8-tiles per warp

    extern __shared__ char dynraw[];
    char* dyn = (char*)(((uintptr_t)dynraw + 1023) & ~(uintptr_t)1023);

    const int tid  = threadIdx.x;
    const int wid  = tid >> 5;
    const int lane = tid & 31;
    const int m0w  = (wid & 3) * 32;
    const int n0w  = (wid >> 2) * (BN / 2);
    const int NS   = K >> 6;

    float acc[2][NT][4];
#pragma unroll
    for (int mt = 0; mt < 2; mt++)
#pragma unroll
        for (int nt = 0; nt < NT; nt++)
#pragma unroll
            for (int v = 0; v < 4; v++) acc[mt][nt][v] = 0.f;

    auto issue = [&](int s, int st){
        char* buf = dyn + st * STG;
        uint32_t ba = smem_u32(buf);
        const __half* ap[2] = { Ahp, Alp };
#pragma unroll
        for (int p = 0; p < ASPLIT; p++)
#pragma unroll
            for (int it = 0; it < 4; it++) {
                int c = tid + it * 256;          // 0..1023
                int row = c >> 3, kc = c & 7;
                const void* src = ap[p] + (size_t)(blockIdx.y * 128 + row) * K + s * 64 + kc * 8;
                cpasync16(ba + p * ASTG + SWZ((uint32_t)(row * 128 + kc * 16)), src);
            }
#pragma unroll
        for (int it = 0; it < BIT; it++) {
            int c = tid + it * 256;
            int row = c >> 3, kc = c & 7;
            const void* src = Bp + (size_t)(blockIdx.x * BN + row) * K + s * 64 + kc * 8;
            cpasync16(ba + ASPLIT * ASTG + SWZ((uint32_t)(row * 128 + kc * 16)), src);
        }
    };

    issue(0, 0); cpcommit();
    issue(1, 1); cpcommit();

    const int arow = lane & 15;
    const int brow = (lane & 7) | ((lane >> 1) & 8);
    const int asel = lane >> 4;
    const int bsel = (lane >> 3) & 1;

    for (int s = 0; s < NS; s++) {
        const int st = s % 3;
        if (s + 2 < NS) issue(s + 2, (s + 2) % 3);
        cpcommit();
        cpwait<2>();
        __syncthreads();

        const uint32_t bAh = smem_u32(dyn + st * STG);
        const uint32_t bAl = bAh + ASTG;
        const uint32_t bB  = bAh + ASPLIT * ASTG;

#pragma unroll
        for (int ks = 0; ks < 4; ks++) {
            uint32_t ah[2][4], al[2][4];
            const int achunk = (ks << 1) + asel;
#pragma unroll
            for (int mt = 0; mt < 2; mt++) {
                uint32_t off = SWZ((uint32_t)((m0w + mt * 16 + arow) * 128 + achunk * 16));
                ldm4(ah[mt], bAh + off);
                if (ASPLIT == 2) ldm4(al[mt], bAl + off);
            }
            uint32_t bh[NT][2];
            const int bchunk = (ks << 1) + bsel;
#pragma unroll
            for (int np = 0; np < NT / 2; np++) {
                uint32_t off = SWZ((uint32_t)((n0w + np * 16 + brow) * 128 + bchunk * 16));
                uint32_t r[4];
                ldm4(r, bB + off);
                bh[2*np][0] = r[0]; bh[2*np][1] = r[1];
                bh[2*np+1][0] = r[2]; bh[2*np+1][1] = r[3];
            }
#pragma unroll
            for (int mt = 0; mt < 2; mt++)
#pragma unroll
                for (int nt = 0; nt < NT; nt++)
                    mma_f16(acc[mt][nt], ah[mt], bh[nt]);
            if (ASPLIT == 2) {
#pragma unroll
                for (int mt = 0; mt < 2; mt++)
#pragma unroll
                    for (int nt = 0; nt < NT; nt++)
                        mma_f16(acc[mt][nt], al[mt], bh[nt]);
            }
        }
        __syncthreads();
    }

    // ---------- epilogue ----------
    float part[14];
    if (MODE == 3) {
#pragma unroll
        for (int v = 0; v < 14; v++) part[v] = 0.f;
    }
#pragma unroll
    for (int mt = 0; mt < 2; mt++) {
        const int gm = blockIdx.y * 128 + m0w + mt * 16 + (lane >> 2);
#pragma unroll
        for (int nt = 0; nt < NT; nt++) {
            const int gn = blockIdx.x * BN + n0w + nt * 8 + ((lane & 3) << 1);
            const size_t o0 = (size_t)gm * ldn + gn;
            const size_t o1 = (size_t)(gm + 8) * ldn + gn;
            if (MODE == 0) {
                float2 bv = *(const float2*)(bias + gn);
                float2 r0, r1;
                r0.x = acc[mt][nt][0] + bv.x;  r0.y = acc[mt][nt][1] + bv.y;
                r1.x = acc[mt][nt][2] + bv.x;  r1.y = acc[mt][nt][3] + bv.y;
                *(float2*)(C + o0) = r0;
                *(float2*)(C + o1) = r1;
            } else if (MODE == 1) {
                float2 d0 = *(const float2*)(Dm + o0);
                float2 d1 = *(const float2*)(Dm + o1);
                float t0 = tanhf(acc[mt][nt][0] + d0.x);
                float t1 = tanhf(acc[mt][nt][1] + d0.y);
                float t2 = tanhf(acc[mt][nt][2] + d1.x);
                float t3 = tanhf(acc[mt][nt][3] + d1.y);
                *(__half2*)(Chp + o0) = split_hi(t0, t1);
                *(__half2*)(Chp + o1) = split_hi(t2, t3);
            } else if (MODE == 2) {
                float2 bv = *(const float2*)(bias + gn);
                float f0 = acc[mt][nt][0] + bv.x;
                float f1 = acc[mt][nt][1] + bv.y;
                float f2 = acc[mt][nt][2] + bv.x;
                float f3 = acc[mt][nt][3] + bv.y;
                float2 z0 = *(const float2*)(C + o0);
                float2 z1 = *(const float2*)(C + o1);
                float2 gg0 = { f0 - z0.x, f1 - z0.y };
                float2 gg1 = { f2 - z1.x, f3 - z1.y };
                *(float2*)(Ghs + o0) = gg0;
                *(float2*)(Ghs + o1) = gg1;
                *(float2*)(Zhs + o0) = z0;
                *(float2*)(Zhs + o1) = z1;
                float2 w0 = { f0, f1 }, w1 = { f2, f3 };
                *(float2*)(C + o0) = w0;
                *(float2*)(C + o1) = w1;
                *(__half2*)(Chp + o0) = split_hi(f0, f1);
                *(__half2*)(Chp + o1) = split_hi(f2, f3);
            } else {
                // MODE 3: f = acc + bias; write f; accumulate reduce partials
                float2 bv = *(const float2*)(bias + gn);
                float fr[4];
                fr[0] = acc[mt][nt][0] + bv.x;
                fr[1] = acc[mt][nt][1] + bv.y;
                fr[2] = acc[mt][nt][2] + bv.x;
                fr[3] = acc[mt][nt][3] + bv.y;
                *(float2*)(C + o0) = *(float2*)&fr[0];
                *(float2*)(C + o1) = *(float2*)&fr[2];
                float2 z0 = *(const float2*)(Dm + o0);
                float2 z1 = *(const float2*)(Dm + o1);
                float gg[4] = { fr[0] - z0.x, fr[1] - z0.y, fr[2] - z1.x, fr[3] - z1.y };
                float2 h1a = *(const float2*)(&g_Gh[s1][0] + o0);
                float2 h1b = *(const float2*)(&g_Gh[s1][0] + o1);
                float2 h2a = *(const float2*)(&g_Gh[s2][0] + o0);
                float2 h2b = *(const float2*)(&g_Gh[s2][0] + o1);
                float2 h3a = *(const float2*)(&g_Gh[s3][0] + o0);
                float2 h3b = *(const float2*)(&g_Gh[s3][0] + o1);
                float2 h4a = *(const float2*)(&g_Gh[s4][0] + o0);
                float2 h4b = *(const float2*)(&g_Gh[s4][0] + o1);
                float hv[4][4] = {
                    { h1a.x, h1a.y, h1b.x, h1b.y },
                    { h2a.x, h2a.y, h2b.x, h2b.y },
                    { h3a.x, h3a.y, h3b.x, h3b.y },
                    { h4a.x, h4a.y, h4b.x, h4b.y }
                };
#pragma unroll
                for (int e = 0; e < 4; e++) {
                    float g  = gg[e];
                    float d0 = g - hv[0][e];
                    float d1 = g - hv[1][e];
                    float d2 = g - hv[2][e];
                    float d3 = g - hv[3][e];
                    part[0] += d0 * d0; part[1] += d0 * d1; part[2] += d0 * d2; part[3] += d0 * d3;
                    part[4] += d1 * d1; part[5] += d1 * d2; part[6] += d1 * d3;
                    part[7] += d2 * d2; part[8] += d2 * d3; part[9] += d3 * d3;
                    part[10] += d0 * g; part[11] += d1 * g; part[12] += d2 * g; part[13] += d3 * g;
                }
            }
        }
    }

    if (MODE == 3) {
        __shared__ float sred[8][14];
#pragma unroll
        for (int v = 0; v < 14; v++)
#pragma unroll
            for (int o = 16; o > 0; o >>= 1)
                part[v] += __shfl_down_sync(0xffffffffu, part[v], o);
        if (lane == 0) {
#pragma unroll
            for (int v = 0; v < 14; v++) sred[wid][v] = part[v];
        }
        __syncthreads();
        if (tid < 14) {
            float ssum = 0.f;
#pragma unroll
            for (int w = 0; w < 8; w++) ssum += sred[w][tid];
            int batch = blockIdx.y >> 3;   // 128 rows/block, 1024 rows/batch
            atomicAdd(&g_red[batch * 14 + tid], ssum);
        }
    }
}

// ---------------- one-time converters ----------------
__global__ void conv_wT(const float* __restrict__ W,
                        __half* __restrict__ T, int K, int N)
{
    __shared__ float t[32][33];
    int n0 = blockIdx.x * 32, k0 = blockIdx.y * 32;
    int tx = threadIdx.x, ty = threadIdx.y;   // 32 x 8
#pragma unroll
    for (int r = 0; r < 32; r += 8)
        t[ty + r][tx] = W[(size_t)(k0 + ty + r) * N + n0 + tx];
    __syncthreads();
#pragma unroll
    for (int r = 0; r < 32; r += 8) {
        float v = t[tx][ty + r];
        T[(size_t)(n0 + ty + r) * K + k0 + tx] = __float2half_rn(v);
    }
}
__global__ void conv_plane(const float* __restrict__ X,
                           __half* __restrict__ Xh, __half* __restrict__ Xl)
{
    int i = blockIdx.x * blockDim.x + threadIdx.x;
    float4 v = ((const float4*)X)[i];
    __half2 h01 = split_hi(v.x, v.y), h23 = split_hi(v.z, v.w);
    ((__half2*)Xh)[i*2]   = h01;
    ((__half2*)Xh)[i*2+1] = h23;
    ((__half2*)Xl)[i*2]   = split_lo(v.x, v.y, h01);
    ((__half2*)Xl)[i*2+1] = split_lo(v.z, v.w, h23);
}

// ---------------- iteration 0: h = tanh(xb) ----------------
__global__ void tanh_map(const float* __restrict__ src, __half* __restrict__ Hh)
{
    int i = blockIdx.x * blockDim.x + threadIdx.x;
    float4 v = ((const float4*)src)[i];
    v.x = tanhf(v.x); v.y = tanhf(v.y); v.z = tanhf(v.z); v.w = tanhf(v.w);
    ((__half2*)Hh)[i*2]   = split_hi(v.x, v.y);
    ((__half2*)Hh)[i*2+1] = split_hi(v.z, v.w);
}

// ---------------- Anderson mixed update (fused gamma solve, + z plane) ----------------
__global__ void upd_anderson(const float* __restrict__ f, float* __restrict__ z,
                             float* __restrict__ dst,
                             int s1, int s2, int s3, int s4, int sw)
{
    __shared__ float sg[8];
    if (threadIdx.x < 2)
        solve_gamma(&g_red[threadIdx.x * 14], &sg[threadIdx.x * 4]);
    __syncthreads();

    int i = blockIdx.x * blockDim.x + threadIdx.x;
    int b = i >> 17;
    float ga0 = sg[b * 4 + 0];
    float ga1 = sg[b * 4 + 1];
    float ga2 = sg[b * 4 + 2];
    float ga3 = sg[b * 4 + 3];

    float4 fv = ((const float4*)f)[i];
    float4 zv = ((const float4*)z)[i];
    float4 G1 = ((const float4*)g_Gh[s1])[i];
    float4 G2 = ((const float4*)g_Gh[s2])[i];
    float4 G3 = ((const float4*)g_Gh[s3])[i];
    float4 G4 = ((const float4*)g_Gh[s4])[i];
    float4 Z1 = ((const float4*)g_Zh[s1])[i];
    float4 Z2 = ((const float4*)g_Zh[s2])[i];
    float4 Z3 = ((const float4*)g_Zh[s3])[i];
    float4 Z4 = ((const float4*)g_Zh[s4])[i];

    float4 gv, ov;
    float* fa = (float*)&fv;  float* za = (float*)&zv;
    float* g1 = (float*)&G1;  float* g2 = (float*)&G2;
    float* g3 = (float*)&G3;  float* g4 = (float*)&G4;
    float* z1 = (float*)&Z1;  float* z2 = (float*)&Z2;
    float* z3 = (float*)&Z3;  float* z4 = (float*)&Z4;
    float* gva = (float*)&gv; float* ova = (float*)&ov;

#pragma unroll
    for (int c = 0; c < 4; c++) {
        float zc = za[c];
        float g  = fa[c] - zc;
        float corr = ga0 * ((zc - z1[c]) + (g - g1[c]))
                   + ga1 * ((zc - z2[c]) + (g - g2[c]))
                   + ga2 * ((zc - z3[c]) + (g - g3[c]))
                   + ga3 * ((zc - z4[c]) + (g - g4[c]));
        gva[c] = g;
        ova[c] = zc + g - corr;
    }
    ((float4*)g_Gh[sw])[i] = gv;
    ((float4*)g_Zh[sw])[i] = zv;
    ((float4*)dst)[i] = ov;
    ((__half2*)g_zp)[i*2]   = split_hi(ov.x, ov.y);
    ((__half2*)g_zp)[i*2+1] = split_hi(ov.z, ov.w);
}

// ---------------- launcher ----------------
extern "C" void kernel_launch(void* const* d_in, const int* in_sizes, int n_in,
                              void* d_out, int out_size)
{
    (void)in_sizes; (void)n_in; (void)out_size;
    const float* x  = (const float*)d_in[0];
    const float* W1 = (const float*)d_in[1];
    const float* Wx = (const float*)d_in[2];
    const float* b1 = (const float*)d_in[3];
    const float* W2 = (const float*)d_in[4];
    const float* b2 = (const float*)d_in[5];
    float* out = (float*)d_out;

    float *xb, *z, *f, *red, *Gh0, *Zh0;
    cudaGetSymbolAddress((void**)&xb,  g_xb);
    cudaGetSymbolAddress((void**)&z,   g_z);
    cudaGetSymbolAddress((void**)&f,   g_f);
    cudaGetSymbolAddress((void**)&red, g_red);
    cudaGetSymbolAddress((void**)&Gh0, g_Gh);
    cudaGetSymbolAddress((void**)&Zh0, g_Zh);
    __half *W1T, *WxT, *W2T, *xh, *xl, *zh, *hh;
    cudaGetSymbolAddress((void**)&W1T, g_W1T);
    cudaGetSymbolAddress((void**)&WxT, g_WxT);
    cudaGetSymbolAddress((void**)&W2T, g_W2T);
    cudaGetSymbolAddress((void**)&xh,  g_xp);  xl = xh + TOT;
    cudaGetSymbolAddress((void**)&zh,  g_zp);
    cudaGetSymbolAddress((void**)&hh,  g_hp);

    const int DYN128X = 3 * (2*128*64*2 + 128*64*2) + 1024;   // ~145 KB (ASPLIT=2, xb)
    const int DYN128S = 3 * (1*128*64*2 + 128*64*2) + 1024;   //  ~97 KB (ASPLIT=1, GEMM1)
    const int DYN64S  = 3 * (1*128*64*2 +  64*64*2) + 1024;   //  ~73 KB (ASPLIT=1, GEMM2)
    cudaFuncSetAttribute(gemm_p<128,0,2>, cudaFuncAttributeMaxDynamicSharedMemorySize, DYN128X);
    cudaFuncSetAttribute(gemm_p<128,1,1>, cudaFuncAttributeMaxDynamicSharedMemorySize, DYN128S);
    cudaFuncSetAttribute(gemm_p<64,2,1>,  cudaFuncAttributeMaxDynamicSharedMemorySize, DYN64S);
    cudaFuncSetAttribute(gemm_p<64,3,1>,  cudaFuncAttributeMaxDynamicSharedMemorySize, DYN64S);

    cudaMemsetAsync(z, 0, (size_t)TOT * sizeof(float));

    // one-time conversions
    dim3 tb(32, 8);
    conv_wT<<<dim3(Fq/32, Dq/32), tb>>>(W1, W1T, Dq, Fq);
    conv_wT<<<dim3(Fq/32, Dq/32), tb>>>(Wx, WxT, Dq, Fq);
    conv_wT<<<dim3(Dq/32, Fq/32), tb>>>(W2, W2T, Fq, Dq);
    conv_plane<<<TOT/4/256, 256>>>(x, xh, xl);

    dim3 g1(Fq / 128, MF / 128);   // 16 x 16
    dim3 g2(Dq / 64,  MF / 128);   // 8 x 16

    // xb = x @ Wx + b1   (x split 2-term: protect the iteration-invariant term)
    gemm_p<128,0,2><<<g1, 256, DYN128X>>>(xh, xl, WxT, b1, nullptr, xb,
                                          nullptr, nullptr, nullptr, Dq, Fq, 0,0,0,0);

    const int upd_blocks = TOT / 4 / 256;
    for (int i = 0; i < 12; i++) {
        // h = tanh(z @ W1 + xb)  (z single fp16 plane: 1 MMA/tile)
        if (i == 0)
            tanh_map<<<(size_t)MF * Fq / 4 / 256, 256>>>(xb, hh);
        else
            gemm_p<128,1,1><<<g1, 256, DYN128S>>>(zh, nullptr, W1T, nullptr, xb, nullptr,
                                                  hh, nullptr, nullptr, Dq, Fq, 0,0,0,0);
        // f = h @ W2 + b2   (h single plane: 1 MMA/tile)
        if (i < 5) {
            // fused: f, g-history, z-history, z_new, z plane
            gemm_p<64,2,1><<<g2, 256, DYN64S>>>(hh, nullptr, W2T, b2, nullptr, z,
                                                zh, Gh0 + (size_t)(i & 3) * TOT,
                                                Zh0 + (size_t)(i & 3) * TOT, Fq, Dq, 0,0,0,0);
        } else {
            const int s1 = (i - 1) & 3, s2 = (i - 2) & 3, s3 = (i - 3) & 3, s4 = (i - 4) & 3;
            cudaMemsetAsync(red, 0, 28 * sizeof(float));
            // fused: f = h@W2 + b2 AND reduce partials (reads z via Dm)
            gemm_p<64,3,1><<<g2, 256, DYN64S>>>(hh, nullptr, W2T, b2, z, f,
                                                nullptr, nullptr, nullptr,
                                                Fq, Dq, s1, s2, s3, s4);
            float* dst = (i == 11) ? out : z;
            upd_anderson<<<upd_blocks, 256>>>(f, z, dst, s1, s2, s3, s4, i & 3);
        }
    }
}

// round 17
// speedup vs baseline: 2.1153x; 1.0579x over previous
#include <cuda_runtime.h>
#include <cuda_fp16.h>
#include <math.h>
#include <stdint.h>

// Problem constants
#define Bq   2
#define Sq   1024
#define Dq   512
#define Fq   2048
#define MF   (Bq*Sq)          // 2048 GEMM rows
#define FLAT (Sq*Dq)          // 524288 per-batch flat size (2^19)
#define TOT  (Bq*FLAT)        // 1048576
#define LAMv 1e-4f

// ---------------- scratch (no allocations allowed) ----------------
__device__ float g_xb[(size_t)MF*Fq];   // x@Wx + b1 (16MB)
__device__ float g_z [TOT];             // current z (fp32)
__device__ float g_f [TOT];             // f(z) (only used i>=5)
__device__ float g_Gh[4][TOT];          // g history, circular (for HTH/HTy)
__device__ float g_Fh[4][TOT];          // f history, circular (corr = ga.(f - f_i))
__device__ float g_red[2*14];
__device__ float g_gamma[2*4];

// fp16 planes: weights single; x, z, h single
__device__ __half g_W1T[(size_t)Fq*Dq];  // [N=2048][K=512]
__device__ __half g_WxT[(size_t)Fq*Dq];
__device__ __half g_W2T[(size_t)Dq*Fq];  // [512][2048]
__device__ __half g_xp [TOT];
__device__ __half g_zp [TOT];
__device__ __half g_hp [(size_t)MF*Fq];

// ======================= helpers =======================
__device__ __forceinline__ uint32_t smem_u32(const void* p){
    uint32_t a;
    asm("{ .reg .u64 t; cvta.to.shared.u64 t, %1; cvt.u32.u64 %0, t; }" : "=r"(a) : "l"(p));
    return a;
}
#define SWZ(o) ((o) ^ (((o) >> 3) & 0x70))

__device__ __forceinline__ void ldm4(uint32_t* r, uint32_t addr){
    asm volatile("ldmatrix.sync.aligned.m8n8.x4.shared.b16 {%0,%1,%2,%3}, [%4];"
        : "=r"(r[0]), "=r"(r[1]), "=r"(r[2]), "=r"(r[3]) : "r"(addr));
}
__device__ __forceinline__ void mma_f16(float* c, const uint32_t* a, const uint32_t* b){
    asm volatile("mma.sync.aligned.m16n8k16.row.col.f32.f16.f16.f32 "
        "{%0,%1,%2,%3}, {%4,%5,%6,%7}, {%8,%9}, {%0,%1,%2,%3};"
        : "+f"(c[0]), "+f"(c[1]), "+f"(c[2]), "+f"(c[3])
        : "r"(a[0]), "r"(a[1]), "r"(a[2]), "r"(a[3]), "r"(b[0]), "r"(b[1]));
}
__device__ __forceinline__ void cpasync16(uint32_t dst, const void* src){
    asm volatile("cp.async.cg.shared.global [%0], [%1], 16;" :: "r"(dst), "l"(src));
}
__device__ __forceinline__ void cpcommit(){ asm volatile("cp.async.commit_group;" ::: "memory"); }
template<int N> __device__ __forceinline__ void cpwait(){
    asm volatile("cp.async.wait_group %0;" :: "n"(N) : "memory");
}
__device__ __forceinline__ __half2 pack_h2(float a, float b){
    return __floats2half2_rn(a, b);
}

// ---------------- 4x4 Schur-complement solve (device, replicates reference) ----------------
__device__ __forceinline__ void inv2x2d(const float m[4], float o[4])
{
    float invDet = 1.f / (m[0] * m[3] - m[1] * m[2] + 1e-6f);
    o[0] =  m[3] * invDet; o[1] = -m[1] * invDet;
    o[2] = -m[2] * invDet; o[3] =  m[0] * invDet;
}
__device__ __forceinline__ void mul2x2d(const float a[4], const float b[4], float o[4])
{
    o[0] = a[0] * b[0] + a[1] * b[2]; o[1] = a[0] * b[1] + a[1] * b[3];
    o[2] = a[2] * b[0] + a[3] * b[2]; o[3] = a[2] * b[1] + a[3] * b[3];
}
__device__ void solve_gamma(const float* r, float* gam)
{
    float H[4][4];
    H[0][0] = r[0] + LAMv; H[0][1] = r[1];        H[0][2] = r[2];        H[0][3] = r[3];
    H[1][0] = r[1];        H[1][1] = r[4] + LAMv; H[1][2] = r[5];        H[1][3] = r[6];
    H[2][0] = r[2];        H[2][1] = r[5];        H[2][2] = r[7] + LAMv; H[2][3] = r[8];
    H[3][0] = r[3];        H[3][1] = r[6];        H[3][2] = r[8];        H[3][3] = r[9] + LAMv;
    float y[4] = { r[10], r[11], r[12], r[13] };

    float A_[4] = { H[0][0], H[0][1], H[1][0], H[1][1] };
    float Bb[4] = { H[0][2], H[0][3], H[1][2], H[1][3] };
    float C_[4] = { H[2][0], H[2][1], H[3][0], H[3][1] };
    float Dd[4] = { H[2][2], H[2][3], H[3][2], H[3][3] };

    float Ai[4];   inv2x2d(A_, Ai);
    float CAi[4];  mul2x2d(C_, Ai, CAi);
    float CAiB[4]; mul2x2d(CAi, Bb, CAiB);
    float Sch[4]  = { Dd[0] - CAiB[0], Dd[1] - CAiB[1], Dd[2] - CAiB[2], Dd[3] - CAiB[3] };
    float Si[4];   inv2x2d(Sch, Si);
    float SiCAi[4]; mul2x2d(Si, CAi, SiCAi);
    float AiB[4];   mul2x2d(Ai, Bb, AiB);
    float t11[4];   mul2x2d(AiB, SiCAi, t11);
    float b11[4] = { Ai[0] + t11[0], Ai[1] + t11[1], Ai[2] + t11[2], Ai[3] + t11[3] };
    float b12[4];   mul2x2d(AiB, Si, b12);
    b12[0] = -b12[0]; b12[1] = -b12[1]; b12[2] = -b12[2]; b12[3] = -b12[3];

    float inv[4][4] = {
        { b11[0],  b11[1],  b12[0],  b12[1] },
        { b11[2],  b11[3],  b12[2],  b12[3] },
        { -SiCAi[0], -SiCAi[1], Si[0], Si[1] },
        { -SiCAi[2], -SiCAi[3], Si[2], Si[3] }
    };
#pragma unroll
    for (int j = 0; j < 4; j++)
        gam[j] = inv[j][0] * y[0] + inv[j][1] * y[1]
               + inv[j][2] * y[2] + inv[j][3] * y[3];
}

// ======================= pipelined fp16 mma.sync GEMM =======================
// CTA tile 128(M) x BN, K-slab 64, SW128, 3-stage cp.async, 2 CTAs/SM.
// A: [M x K] fp16 single plane.  B: [N x K] fp16 (weights).
// MODE 0: C fp32 = acc + bias[n]
// MODE 1: t = tanh(acc + Dm[m][n]); write Chp fp16 plane
// MODE 2: f = acc + bias[n]; fused upd_simple: g = f - C(z); Ghs=g, Fhs=f,
//         C=f (new z), Chp = half(f) (z plane)
// MODE 3: f = acc + bias[n]; C=f; fused reduce_k partials (Dm holds z input)
template<int BN, int MODE>
__global__ __launch_bounds__(256, 2) void gemm_p(
    const __half* __restrict__ Ap, const __half* __restrict__ Bp,
    const float* __restrict__ bias, const float* __restrict__ Dm,
    float* __restrict__ C,
    __half* __restrict__ Chp,
    float* __restrict__ Ghs, float* __restrict__ Fhs,
    int K, int ldn, int s1, int s2, int s3, int s4)
{
    constexpr int ASTG = 128 * 64 * 2;         // A plane per stage (16 KB)
    constexpr int BSTG = BN  * 64 * 2;         // B plane per stage
    constexpr int STG  = ASTG + BSTG;          // stage size
    constexpr int BIT  = (BN * 8) / 256;       // B chunks per thread
    constexpr int NT   = BN / 16;              // n8-tiles per warp

    extern __shared__ char dynraw[];
    char* dyn = (char*)(((uintptr_t)dynraw + 1023) & ~(uintptr_t)1023);

    const int tid  = threadIdx.x;
    const int wid  = tid >> 5;
    const int lane = tid & 31;
    const int m0w  = (wid & 3) * 32;
    const int n0w  = (wid >> 2) * (BN / 2);
    const int NS   = K >> 6;

    float acc[2][NT][4];
#pragma unroll
    for (int mt = 0; mt < 2; mt++)
#pragma unroll
        for (int nt = 0; nt < NT; nt++)
#pragma unroll
            for (int v = 0; v < 4; v++) acc[mt][nt][v] = 0.f;

    auto issue = [&](int s, int st){
        uint32_t ba = smem_u32(dyn + st * STG);
#pragma unroll
        for (int it = 0; it < 4; it++) {
            int c = tid + it * 256;          // 0..1023
            int row = c >> 3, kc = c & 7;
            const void* src = Ap + (size_t)(blockIdx.y * 128 + row) * K + s * 64 + kc * 8;
            cpasync16(ba + SWZ((uint32_t)(row * 128 + kc * 16)), src);
        }
#pragma unroll
        for (int it = 0; it < BIT; it++) {
            int c = tid + it * 256;
            int row = c >> 3, kc = c & 7;
            const void* src = Bp + (size_t)(blockIdx.x * BN + row) * K + s * 64 + kc * 8;
            cpasync16(ba + ASTG + SWZ((uint32_t)(row * 128 + kc * 16)), src);
        }
    };

    issue(0, 0); cpcommit();
    issue(1, 1); cpcommit();

    const int arow = lane & 15;
    const int brow = (lane & 7) | ((lane >> 1) & 8);
    const int asel = lane >> 4;
    const int bsel = (lane >> 3) & 1;

    for (int s = 0; s < NS; s++) {
        const int st = s % 3;
        if (s + 2 < NS) issue(s + 2, (s + 2) % 3);
        cpcommit();
        cpwait<2>();
        __syncthreads();

        const uint32_t bA = smem_u32(dyn + st * STG);
        const uint32_t bB = bA + ASTG;

#pragma unroll
        for (int ks = 0; ks < 4; ks++) {
            uint32_t ah[2][4];
            const int achunk = (ks << 1) + asel;
#pragma unroll
            for (int mt = 0; mt < 2; mt++) {
                uint32_t off = SWZ((uint32_t)((m0w + mt * 16 + arow) * 128 + achunk * 16));
                ldm4(ah[mt], bA + off);
            }
            uint32_t bh[NT][2];
            const int bchunk = (ks << 1) + bsel;
#pragma unroll
            for (int np = 0; np < NT / 2; np++) {
                uint32_t off = SWZ((uint32_t)((n0w + np * 16 + brow) * 128 + bchunk * 16));
                uint32_t r[4];
                ldm4(r, bB + off);
                bh[2*np][0] = r[0]; bh[2*np][1] = r[1];
                bh[2*np+1][0] = r[2]; bh[2*np+1][1] = r[3];
            }
#pragma unroll
            for (int mt = 0; mt < 2; mt++)
#pragma unroll
                for (int nt = 0; nt < NT; nt++)
                    mma_f16(acc[mt][nt], ah[mt], bh[nt]);
        }
        __syncthreads();
    }

    // ---------- epilogue ----------
    float part[14];
    if (MODE == 3) {
#pragma unroll
        for (int v = 0; v < 14; v++) part[v] = 0.f;
    }
#pragma unroll
    for (int mt = 0; mt < 2; mt++) {
        const int gm = blockIdx.y * 128 + m0w + mt * 16 + (lane >> 2);
#pragma unroll
        for (int nt = 0; nt < NT; nt++) {
            const int gn = blockIdx.x * BN + n0w + nt * 8 + ((lane & 3) << 1);
            const size_t o0 = (size_t)gm * ldn + gn;
            const size_t o1 = (size_t)(gm + 8) * ldn + gn;
            if (MODE == 0) {
                float2 bv = *(const float2*)(bias + gn);
                float2 r0, r1;
                r0.x = acc[mt][nt][0] + bv.x;  r0.y = acc[mt][nt][1] + bv.y;
                r1.x = acc[mt][nt][2] + bv.x;  r1.y = acc[mt][nt][3] + bv.y;
                *(float2*)(C + o0) = r0;
                *(float2*)(C + o1) = r1;
            } else if (MODE == 1) {
                float2 d0 = *(const float2*)(Dm + o0);
                float2 d1 = *(const float2*)(Dm + o1);
                float t0 = tanhf(acc[mt][nt][0] + d0.x);
                float t1 = tanhf(acc[mt][nt][1] + d0.y);
                float t2 = tanhf(acc[mt][nt][2] + d1.x);
                float t3 = tanhf(acc[mt][nt][3] + d1.y);
                *(__half2*)(Chp + o0) = pack_h2(t0, t1);
                *(__half2*)(Chp + o1) = pack_h2(t2, t3);
            } else if (MODE == 2) {
                float2 bv = *(const float2*)(bias + gn);
                float f0 = acc[mt][nt][0] + bv.x;
                float f1 = acc[mt][nt][1] + bv.y;
                float f2 = acc[mt][nt][2] + bv.x;
                float f3 = acc[mt][nt][3] + bv.y;
                float2 z0 = *(const float2*)(C + o0);
                float2 z1 = *(const float2*)(C + o1);
                float2 gg0 = { f0 - z0.x, f1 - z0.y };
                float2 gg1 = { f2 - z1.x, f3 - z1.y };
                *(float2*)(Ghs + o0) = gg0;
                *(float2*)(Ghs + o1) = gg1;
                float2 w0 = { f0, f1 }, w1 = { f2, f3 };
                *(float2*)(Fhs + o0) = w0;
                *(float2*)(Fhs + o1) = w1;
                *(float2*)(C + o0) = w0;
                *(float2*)(C + o1) = w1;
                *(__half2*)(Chp + o0) = pack_h2(f0, f1);
                *(__half2*)(Chp + o1) = pack_h2(f2, f3);
            } else {
                // MODE 3: f = acc + bias; write f; accumulate reduce partials
                float2 bv = *(const float2*)(bias + gn);
                float fr[4];
                fr[0] = acc[mt][nt][0] + bv.x;
                fr[1] = acc[mt][nt][1] + bv.y;
                fr[2] = acc[mt][nt][2] + bv.x;
                fr[3] = acc[mt][nt][3] + bv.y;
                *(float2*)(C + o0) = *(float2*)&fr[0];
                *(float2*)(C + o1) = *(float2*)&fr[2];
                float2 z0 = *(const float2*)(Dm + o0);
                float2 z1 = *(const float2*)(Dm + o1);
                float gg[4] = { fr[0] - z0.x, fr[1] - z0.y, fr[2] - z1.x, fr[3] - z1.y };
                float2 h1a = *(const float2*)(&g_Gh[s1][0] + o0);
                float2 h1b = *(const float2*)(&g_Gh[s1][0] + o1);
                float2 h2a = *(const float2*)(&g_Gh[s2][0] + o0);
                float2 h2b = *(const float2*)(&g_Gh[s2][0] + o1);
                float2 h3a = *(const float2*)(&g_Gh[s3][0] + o0);
                float2 h3b = *(const float2*)(&g_Gh[s3][0] + o1);
                float2 h4a = *(const float2*)(&g_Gh[s4][0] + o0);
                float2 h4b = *(const float2*)(&g_Gh[s4][0] + o1);
                float hv[4][4] = {
                    { h1a.x, h1a.y, h1b.x, h1b.y },
                    { h2a.x, h2a.y, h2b.x, h2b.y },
                    { h3a.x, h3a.y, h3b.x, h3b.y },
                    { h4a.x, h4a.y, h4b.x, h4b.y }
                };
#pragma unroll
                for (int e = 0; e < 4; e++) {
                    float g  = gg[e];
                    float d0 = g - hv[0][e];
                    float d1 = g - hv[1][e];
                    float d2 = g - hv[2][e];
                    float d3 = g - hv[3][e];
                    part[0] += d0 * d0; part[1] += d0 * d1; part[2] += d0 * d2; part[3] += d0 * d3;
                    part[4] += d1 * d1; part[5] += d1 * d2; part[6] += d1 * d3;
                    part[7] += d2 * d2; part[8] += d2 * d3; part[9] += d3 * d3;
                    part[10] += d0 * g; part[11] += d1 * g; part[12] += d2 * g; part[13] += d3 * g;
                }
            }
        }
    }

    if (MODE == 3) {
        __shared__ float sred[8][14];
#pragma unroll
        for (int v = 0; v < 14; v++)
#pragma unroll
            for (int o = 16; o > 0; o >>= 1)
                part[v] += __shfl_down_sync(0xffffffffu, part[v], o);
        if (lane == 0) {
#pragma unroll
            for (int v = 0; v < 14; v++) sred[wid][v] = part[v];
        }
        __syncthreads();
        if (tid < 14) {
            float ssum = 0.f;
#pragma unroll
            for (int w = 0; w < 8; w++) ssum += sred[w][tid];
            int batch = blockIdx.y >> 3;   // 128 rows/block, 1024 rows/batch
            atomicAdd(&g_red[batch * 14 + tid], ssum);
        }
    }
}

// ---------------- one-time converters ----------------
__global__ void conv_wT(const float* __restrict__ W,
                        __half* __restrict__ T, int K, int N)
{
    __shared__ float t[32][33];
    int n0 = blockIdx.x * 32, k0 = blockIdx.y * 32;
    int tx = threadIdx.x, ty = threadIdx.y;   // 32 x 8
#pragma unroll
    for (int r = 0; r < 32; r += 8)
        t[ty + r][tx] = W[(size_t)(k0 + ty + r) * N + n0 + tx];
    __syncthreads();
#pragma unroll
    for (int r = 0; r < 32; r += 8) {
        float v = t[tx][ty + r];
        T[(size_t)(n0 + ty + r) * K + k0 + tx] = __float2half_rn(v);
    }
}
__global__ void conv_plane(const float* __restrict__ X, __half* __restrict__ Xh)
{
    int i = blockIdx.x * blockDim.x + threadIdx.x;
    float4 v = ((const float4*)X)[i];
    ((__half2*)Xh)[i*2]   = pack_h2(v.x, v.y);
    ((__half2*)Xh)[i*2+1] = pack_h2(v.z, v.w);
}

// ---------------- iteration 0: h = tanh(xb) ----------------
__global__ void tanh_map(const float* __restrict__ src, __half* __restrict__ Hh)
{
    int i = blockIdx.x * blockDim.x + threadIdx.x;
    float4 v = ((const float4*)src)[i];
    v.x = tanhf(v.x); v.y = tanhf(v.y); v.z = tanhf(v.z); v.w = tanhf(v.w);
    ((__half2*)Hh)[i*2]   = pack_h2(v.x, v.y);
    ((__half2*)Hh)[i*2+1] = pack_h2(v.z, v.w);
}

// ---------------- Anderson mixed update (fused gamma solve; f-history form) ----------------
// corr = sum_i gamma_i * (f - Fh[s_i])   [== (z - z_i) + (g - g_i), BETA = 1]
__global__ void upd_anderson(const float* __restrict__ f, float* __restrict__ z,
                             float* __restrict__ dst,
                             int s1, int s2, int s3, int s4, int sw)
{
    __shared__ float sg[8];
    if (threadIdx.x < 2)
        solve_gamma(&g_red[threadIdx.x * 14], &sg[threadIdx.x * 4]);
    __syncthreads();

    int i = blockIdx.x * blockDim.x + threadIdx.x;
    int b = i >> 17;
    float ga0 = sg[b * 4 + 0];
    float ga1 = sg[b * 4 + 1];
    float ga2 = sg[b * 4 + 2];
    float ga3 = sg[b * 4 + 3];

    float4 fv = ((const float4*)f)[i];
    float4 zv = ((const float4*)z)[i];
    float4 F1 = ((const float4*)g_Fh[s1])[i];
    float4 F2 = ((const float4*)g_Fh[s2])[i];
    float4 F3 = ((const float4*)g_Fh[s3])[i];
    float4 F4 = ((const float4*)g_Fh[s4])[i];

    float4 gv, ov;
    float* fa = (float*)&fv;  float* za = (float*)&zv;
    float* f1 = (float*)&F1;  float* f2 = (float*)&F2;
    float* f3 = (float*)&F3;  float* f4 = (float*)&F4;
    float* gva = (float*)&gv; float* ova = (float*)&ov;

#pragma unroll
    for (int c = 0; c < 4; c++) {
        float fc = fa[c];
        float g  = fc - za[c];
        float corr = ga0 * (fc - f1[c]) + ga1 * (fc - f2[c])
                   + ga2 * (fc - f3[c]) + ga3 * (fc - f4[c]);
        gva[c] = g;
        ova[c] = fc - corr;          // z + g - corr with BETA = 1
    }
    ((float4*)g_Gh[sw])[i] = gv;
    ((float4*)g_Fh[sw])[i] = fv;
    ((float4*)dst)[i] = ov;
    ((__half2*)g_zp)[i*2]   = pack_h2(ov.x, ov.y);
    ((__half2*)g_zp)[i*2+1] = pack_h2(ov.z, ov.w);
}

// ---------------- launcher ----------------
extern "C" void kernel_launch(void* const* d_in, const int* in_sizes, int n_in,
                              void* d_out, int out_size)
{
    (void)in_sizes; (void)n_in; (void)out_size;
    const float* x  = (const float*)d_in[0];
    const float* W1 = (const float*)d_in[1];
    const float* Wx = (const float*)d_in[2];
    const float* b1 = (const float*)d_in[3];
    const float* W2 = (const float*)d_in[4];
    const float* b2 = (const float*)d_in[5];
    float* out = (float*)d_out;

    float *xb, *z, *f, *red, *Gh0, *Fh0;
    cudaGetSymbolAddress((void**)&xb,  g_xb);
    cudaGetSymbolAddress((void**)&z,   g_z);
    cudaGetSymbolAddress((void**)&f,   g_f);
    cudaGetSymbolAddress((void**)&red, g_red);
    cudaGetSymbolAddress((void**)&Gh0, g_Gh);
    cudaGetSymbolAddress((void**)&Fh0, g_Fh);
    __half *W1T, *WxT, *W2T, *xh, *zh, *hh;
    cudaGetSymbolAddress((void**)&W1T, g_W1T);
    cudaGetSymbolAddress((void**)&WxT, g_WxT);
    cudaGetSymbolAddress((void**)&W2T, g_W2T);
    cudaGetSymbolAddress((void**)&xh,  g_xp);
    cudaGetSymbolAddress((void**)&zh,  g_zp);
    cudaGetSymbolAddress((void**)&hh,  g_hp);

    const int DYN128 = 3 * (128*64*2 + 128*64*2) + 1024;   // ~97 KB
    const int DYN32  = 3 * (128*64*2 +  32*64*2) + 1024;   // ~61 KB
    cudaFuncSetAttribute(gemm_p<128,0>, cudaFuncAttributeMaxDynamicSharedMemorySize, DYN128);
    cudaFuncSetAttribute(gemm_p<128,1>, cudaFuncAttributeMaxDynamicSharedMemorySize, DYN128);
    cudaFuncSetAttribute(gemm_p<32,2>,  cudaFuncAttributeMaxDynamicSharedMemorySize, DYN32);
    cudaFuncSetAttribute(gemm_p<32,3>,  cudaFuncAttributeMaxDynamicSharedMemorySize, DYN32);

    cudaMemsetAsync(z, 0, (size_t)TOT * sizeof(float));

    // one-time conversions
    dim3 tb(32, 8);
    conv_wT<<<dim3(Fq/32, Dq/32), tb>>>(W1, W1T, Dq, Fq);
    conv_wT<<<dim3(Fq/32, Dq/32), tb>>>(Wx, WxT, Dq, Fq);
    conv_wT<<<dim3(Dq/32, Fq/32), tb>>>(W2, W2T, Fq, Dq);
    conv_plane<<<TOT/4/256, 256>>>(x, xh);

    dim3 g1(Fq / 128, MF / 128);   // 16 x 16 = 256 CTAs
    dim3 g2(Dq / 32,  MF / 128);   // 16 x 16 = 256 CTAs

    // xb = x @ Wx + b1
    gemm_p<128,0><<<g1, 256, DYN128>>>(xh, WxT, b1, nullptr, xb,
                                       nullptr, nullptr, nullptr, Dq, Fq, 0,0,0,0);

    const int upd_blocks = TOT / 4 / 256;
    for (int i = 0; i < 12; i++) {
        // h = tanh(z @ W1 + xb)
        if (i == 0)
            tanh_map<<<(size_t)MF * Fq / 4 / 256, 256>>>(xb, hh);
        else
            gemm_p<128,1><<<g1, 256, DYN128>>>(zh, W1T, nullptr, xb, nullptr,
                                               hh, nullptr, nullptr, Dq, Fq, 0,0,0,0);
        // f = h @ W2 + b2
        if (i < 5) {
            // fused: f, g-history, f-history, z_new, z plane
            gemm_p<32,2><<<g2, 256, DYN32>>>(hh, W2T, b2, nullptr, z,
                                             zh, Gh0 + (size_t)(i & 3) * TOT,
                                             Fh0 + (size_t)(i & 3) * TOT, Fq, Dq, 0,0,0,0);
        } else {
            const int s1 = (i - 1) & 3, s2 = (i - 2) & 3, s3 = (i - 3) & 3, s4 = (i - 4) & 3;
            cudaMemsetAsync(red, 0, 28 * sizeof(float));
            // fused: f = h@W2 + b2 AND reduce partials (reads z via Dm)
            gemm_p<32,3><<<g2, 256, DYN32>>>(hh, W2T, b2, z, f,
                                             nullptr, nullptr, nullptr,
                                             Fq, Dq, s1, s2, s3, s4);
            float* dst = (i == 11) ? out : z;
            upd_anderson<<<upd_blocks, 256>>>(f, z, dst, s1, s2, s3, s4, i & 3);
        }
    }
}